// round 12
// baseline (speedup 1.0000x reference)
#include <cuda_runtime.h>
#include <cuda_bf16.h>
#include <math.h>
#include <stdint.h>

#define BATCH 8
#define SEQ 1024
#define DMODEL 768
#define NH 12
#define HD 64
#define ATTN_SCALE 0.125f
#define MTOT (BATCH * SEQ)         /* 8192 */
#define NQKV (3 * DMODEL)          /* 2304 */

typedef __nv_bfloat16 bf16;

// ---------------------------------------------------------------------------
// Scratch — fp32 only (proven-safe static layout)
// ---------------------------------------------------------------------------
__device__ float g_q[BATCH * NH * SEQ * HD];
__device__ float g_k[BATCH * NH * SEQ * HD];
__device__ float g_v[BATCH * NH * SEQ * HD];
__device__ float g_ctx[BATCH * NH * SEQ * HD];
__device__ float g_wqkvT[NQKV * DMODEL];      // [N][K] fp32
__device__ float g_wprojT[DMODEL * DMODEL];   // [N][K] fp32

// ---------------------------------------------------------------------------
// HMMA helper (m16n8k16, bf16 in / fp32 accumulate)
// ---------------------------------------------------------------------------
__device__ __forceinline__ void mma16816(float* c, const uint32_t* a,
                                         const uint32_t* b) {
    asm volatile(
        "mma.sync.aligned.m16n8k16.row.col.f32.bf16.bf16.f32 "
        "{%0,%1,%2,%3}, {%4,%5,%6,%7}, {%8,%9}, {%0,%1,%2,%3};"
        : "+f"(c[0]), "+f"(c[1]), "+f"(c[2]), "+f"(c[3])
        : "r"(a[0]), "r"(a[1]), "r"(a[2]), "r"(a[3]), "r"(b[0]), "r"(b[1]));
}

__device__ __forceinline__ void split2(float v0, float v1,
                                       __nv_bfloat162& h, __nv_bfloat162& l) {
    bf16 h0 = __float2bfloat16(v0), h1 = __float2bfloat16(v1);
    h = __halves2bfloat162(h0, h1);
    l = __halves2bfloat162(__float2bfloat16(v0 - __bfloat162float(h0)),
                           __float2bfloat16(v1 - __bfloat162float(h1)));
}

// ---------------------------------------------------------------------------
// fp32 transpose: W [K][N] -> WT [N][K]  (R10-proven)
// ---------------------------------------------------------------------------
__global__ void transpose_f32(const float* __restrict__ W,
                              float* __restrict__ WT, int N, int K)
{
    __shared__ float t[32][33];
    int n0 = blockIdx.x * 32, k0 = blockIdx.y * 32;
    int tx = threadIdx.x, ty = threadIdx.y;
#pragma unroll
    for (int i = 0; i < 4; ++i)
        t[ty + i * 8][tx] = W[(size_t)(k0 + ty + i * 8) * N + n0 + tx];
    __syncthreads();
#pragma unroll
    for (int i = 0; i < 4; ++i) {
        int n = ty + i * 8;
        WT[(size_t)(n0 + n) * K + k0 + tx] = t[tx][n];
    }
}

// ---------------------------------------------------------------------------
// Shared HMMA compute for one staged 32-k chunk (bf16 hi/lo smem, stride 40).
// ---------------------------------------------------------------------------
__device__ __forceinline__ void hmma_chunk(
    const bf16* sAh, const bf16* sAl, const bf16* sBh, const bf16* sBl,
    int wrow, int wcol, int g, int tig, float acc[2][8][4])
{
#pragma unroll
    for (int ks = 0; ks < 2; ++ks) {
        const int ko = ks * 16;
        uint32_t ah[2][4], al[2][4];
#pragma unroll
        for (int mi = 0; mi < 2; ++mi) {
            const bf16* p = sAh + (wrow + mi * 16 + g) * 40 + ko + 2 * tig;
            ah[mi][0] = *reinterpret_cast<const uint32_t*>(p);
            ah[mi][1] = *reinterpret_cast<const uint32_t*>(p + 8 * 40);
            ah[mi][2] = *reinterpret_cast<const uint32_t*>(p + 8);
            ah[mi][3] = *reinterpret_cast<const uint32_t*>(p + 8 * 40 + 8);
            const bf16* q = sAl + (wrow + mi * 16 + g) * 40 + ko + 2 * tig;
            al[mi][0] = *reinterpret_cast<const uint32_t*>(q);
            al[mi][1] = *reinterpret_cast<const uint32_t*>(q + 8 * 40);
            al[mi][2] = *reinterpret_cast<const uint32_t*>(q + 8);
            al[mi][3] = *reinterpret_cast<const uint32_t*>(q + 8 * 40 + 8);
        }
        uint32_t bhf[8][2], blf[8][2];
#pragma unroll
        for (int ni = 0; ni < 8; ++ni) {
            const bf16* p = sBh + (wcol + ni * 8 + g) * 40 + ko + 2 * tig;
            bhf[ni][0] = *reinterpret_cast<const uint32_t*>(p);
            bhf[ni][1] = *reinterpret_cast<const uint32_t*>(p + 8);
            const bf16* q = sBl + (wcol + ni * 8 + g) * 40 + ko + 2 * tig;
            blf[ni][0] = *reinterpret_cast<const uint32_t*>(q);
            blf[ni][1] = *reinterpret_cast<const uint32_t*>(q + 8);
        }
#pragma unroll
        for (int mi = 0; mi < 2; ++mi)
#pragma unroll
            for (int ni = 0; ni < 8; ++ni) {
                mma16816(acc[mi][ni], ah[mi], bhf[ni]);
                mma16816(acc[mi][ni], ah[mi], blf[ni]);
                mma16816(acc[mi][ni], al[mi], bhf[ni]);
            }
    }
}

// Stage one [128 rows][32 k] fp32 source tile into split bf16 smem (stride 40)
// Contiguous-in-k source rows; vectorized 8B stores, no transpose.
__device__ __forceinline__ void stage_rows(
    bf16* sh, bf16* sl, const float* __restrict__ G, int rowstride,
    int rowbase, int kt, int tid)
{
#pragma unroll
    for (int it = 0; it < 4; ++it) {
        int id = it * 256 + tid;
        int row = id >> 3, c = id & 7;
        float4 v = *reinterpret_cast<const float4*>(
            &G[(size_t)(rowbase + row) * rowstride + kt + c * 4]);
        __nv_bfloat162 h0, l0, h1, l1;
        split2(v.x, v.y, h0, l0);
        split2(v.z, v.w, h1, l1);
        int o = row * 40 + c * 4;
        *reinterpret_cast<__nv_bfloat162*>(&sh[o]) = h0;
        *reinterpret_cast<__nv_bfloat162*>(&sh[o + 2]) = h1;
        *reinterpret_cast<__nv_bfloat162*>(&sl[o]) = l0;
        *reinterpret_cast<__nv_bfloat162*>(&sl[o + 2]) = l1;
    }
}

// ---------------------------------------------------------------------------
// QKV GEMM: HMMA, both operands contiguous [row][k]; 2 CTAs/SM.
// ---------------------------------------------------------------------------
__global__ __launch_bounds__(256, 2) void qkv_gemm_hmma(
    const float* __restrict__ A, const float* __restrict__ BT,
    const float* __restrict__ bias)
{
    __shared__ bf16 smem[512 * 40];          // 40960 B
    bf16* sAh = smem;
    bf16* sAl = smem + 128 * 40;
    bf16* sBh = smem + 256 * 40;
    bf16* sBl = smem + 384 * 40;

    const int tid = threadIdx.x;
    const int wid = tid >> 5, lane = tid & 31;
    const int nb = blockIdx.x * 128, mb = blockIdx.y * 128;
    const int wrow = (wid & 3) * 32;
    const int wcol = (wid >> 2) * 64;
    const int g = lane >> 2, tig = lane & 3;

    float acc[2][8][4];
#pragma unroll
    for (int mi = 0; mi < 2; ++mi)
#pragma unroll
        for (int ni = 0; ni < 8; ++ni)
#pragma unroll
            for (int r = 0; r < 4; ++r) acc[mi][ni][r] = 0.f;

#pragma unroll 1
    for (int i = 0; i < 24; ++i) {
        stage_rows(sAh, sAl, A, DMODEL, mb, i * 32, tid);
        stage_rows(sBh, sBl, BT, DMODEL, nb, i * 32, tid);
        __syncthreads();
        hmma_chunk(sAh, sAl, sBh, sBl, wrow, wcol, g, tig, acc);
        __syncthreads();
    }

    // Epilogue: scatter fp32 into g_q/g_k/g_v [B,H,S,HD] + bias
#pragma unroll
    for (int mi = 0; mi < 2; ++mi)
#pragma unroll
        for (int ni = 0; ni < 8; ++ni) {
            int col = nb + wcol + ni * 8 + 2 * tig;
            int which = col / DMODEL;
            int rem = col - which * DMODEL;
            int h = rem >> 6, d = rem & 63;
            float* dst = (which == 0) ? g_q : ((which == 1) ? g_k : g_v);
            float b0 = bias[col], b1 = bias[col + 1];
#pragma unroll
            for (int half = 0; half < 2; ++half) {
                int m = mb + wrow + mi * 16 + g + half * 8;
                int bb = m >> 10, s = m & 1023;
                float2 o = make_float2(acc[mi][ni][half * 2 + 0] + b0,
                                       acc[mi][ni][half * 2 + 1] + b1);
                *reinterpret_cast<float2*>(
                    &dst[(((size_t)(bb * NH + h) * SEQ + s) * HD) + d]) = o;
            }
        }
}

// ---------------------------------------------------------------------------
// Proj GEMM: A gathered from g_ctx [B,H,S,HD], B = g_wprojT; 2 CTAs/SM.
// ---------------------------------------------------------------------------
__global__ __launch_bounds__(256, 2) void proj_gemm_hmma(
    const float* __restrict__ BT, const float* __restrict__ bias,
    float* __restrict__ out)
{
    __shared__ bf16 smem[512 * 40];
    bf16* sAh = smem;
    bf16* sAl = smem + 128 * 40;
    bf16* sBh = smem + 256 * 40;
    bf16* sBl = smem + 384 * 40;

    const int tid = threadIdx.x;
    const int wid = tid >> 5, lane = tid & 31;
    const int nb = blockIdx.x * 128, mb = blockIdx.y * 128;
    const int wrow = (wid & 3) * 32;
    const int wcol = (wid >> 2) * 64;
    const int g = lane >> 2, tig = lane & 3;

    float acc[2][8][4];
#pragma unroll
    for (int mi = 0; mi < 2; ++mi)
#pragma unroll
        for (int ni = 0; ni < 8; ++ni)
#pragma unroll
            for (int r = 0; r < 4; ++r) acc[mi][ni][r] = 0.f;

#pragma unroll 1
    for (int i = 0; i < 24; ++i) {
        int kt = i * 32;
        // A: gather from g_ctx (chunk never crosses a head boundary)
#pragma unroll
        for (int it = 0; it < 4; ++it) {
            int id = it * 256 + tid;
            int row = id >> 3, c = id & 7;
            int m = mb + row;
            int bb = m >> 10, s = m & 1023;
            int kg = kt + c * 4;
            int hk = kg >> 6, d = kg & 63;
            float4 v = *reinterpret_cast<const float4*>(
                &g_ctx[(((size_t)(bb * NH + hk) * SEQ + s) * HD) + d]);
            __nv_bfloat162 h0, l0, h1, l1;
            split2(v.x, v.y, h0, l0);
            split2(v.z, v.w, h1, l1);
            int o = row * 40 + c * 4;
            *reinterpret_cast<__nv_bfloat162*>(&sAh[o]) = h0;
            *reinterpret_cast<__nv_bfloat162*>(&sAh[o + 2]) = h1;
            *reinterpret_cast<__nv_bfloat162*>(&sAl[o]) = l0;
            *reinterpret_cast<__nv_bfloat162*>(&sAl[o + 2]) = l1;
        }
        stage_rows(sBh, sBl, BT, DMODEL, nb, kt, tid);
        __syncthreads();
        hmma_chunk(sAh, sAl, sBh, sBl, wrow, wcol, g, tig, acc);
        __syncthreads();
    }

#pragma unroll
    for (int mi = 0; mi < 2; ++mi)
#pragma unroll
        for (int ni = 0; ni < 8; ++ni) {
            int col = nb + wcol + ni * 8 + 2 * tig;
            float b0 = bias[col], b1 = bias[col + 1];
#pragma unroll
            for (int half = 0; half < 2; ++half) {
                int row = mb + wrow + mi * 16 + g + half * 8;
                float2 o = make_float2(acc[mi][ni][half * 2 + 0] + b0,
                                       acc[mi][ni][half * 2 + 1] + b1);
                *reinterpret_cast<float2*>(&out[(size_t)row * DMODEL + col]) = o;
            }
        }
}

// ---------------------------------------------------------------------------
// Flash attention via HMMA (byte-identical to passing R9/R11 kernel)
// ---------------------------------------------------------------------------
#define ATTN_SMEM 126976

__global__ __launch_bounds__(256) void attn_hmma()
{
    extern __shared__ char sm[];
    bf16* sQh = (bf16*)(sm + 0);
    bf16* sQl = (bf16*)(sm + 18432);
    bf16* sKVh = (bf16*)(sm + 36864);
    bf16* sKVl = (bf16*)(sm + 46080);
    float* sPt = (float*)(sm + 55296);
    uint32_t* sPh = (uint32_t*)(sm + 89088);
    uint32_t* sPl = (uint32_t*)(sm + 107520);
    float* sAlpha = (float*)(sm + 125952);
    float* sLinv = (float*)(sm + 126464);

    const int tid = threadIdx.x;
    const int wid = tid >> 5, lane = tid & 31;
    const int qb = blockIdx.x * 128;
    const int h = blockIdx.y, b = blockIdx.z;
    const size_t base = ((size_t)(b * NH + h)) * SEQ * HD;
    const float* Qg = g_q + base;
    const float* Kg = g_k + base;
    const float* Vg = g_v + base;

    const int wrow = (wid & 3) * 32;
    const int wcol = (wid >> 2) * 32;
    const int g = lane >> 2, tig = lane & 3;

#pragma unroll
    for (int it = 0; it < 8; ++it) {
        int id = it * 256 + tid;
        int row = id >> 4, c = id & 15;
        float4 v = *reinterpret_cast<const float4*>(
            &Qg[(size_t)(qb + row) * HD + c * 4]);
        __nv_bfloat162 h0, l0, h1, l1;
        split2(v.x, v.y, h0, l0);
        split2(v.z, v.w, h1, l1);
        *reinterpret_cast<__nv_bfloat162*>(&sQh[row * 72 + c * 4]) = h0;
        *reinterpret_cast<__nv_bfloat162*>(&sQh[row * 72 + c * 4 + 2]) = h1;
        *reinterpret_cast<__nv_bfloat162*>(&sQl[row * 72 + c * 4]) = l0;
        *reinterpret_cast<__nv_bfloat162*>(&sQl[row * 72 + c * 4 + 2]) = l1;
    }

    float oacc[2][4][4];
#pragma unroll
    for (int mi = 0; mi < 2; ++mi)
#pragma unroll
        for (int ni = 0; ni < 4; ++ni)
#pragma unroll
            for (int r = 0; r < 4; ++r) oacc[mi][ni][r] = 0.f;
    float m_run = -1e30f, l_run = 0.f;

    for (int kt = 0; kt < SEQ; kt += 64) {
#pragma unroll
        for (int it = 0; it < 4; ++it) {
            int id = it * 256 + tid;
            int j = id >> 4, c = id & 15;
            float4 v = *reinterpret_cast<const float4*>(
                &Kg[(size_t)(kt + j) * HD + c * 4]);
            __nv_bfloat162 h0, l0, h1, l1;
            split2(v.x, v.y, h0, l0);
            split2(v.z, v.w, h1, l1);
            *reinterpret_cast<__nv_bfloat162*>(&sKVh[j * 72 + c * 4]) = h0;
            *reinterpret_cast<__nv_bfloat162*>(&sKVh[j * 72 + c * 4 + 2]) = h1;
            *reinterpret_cast<__nv_bfloat162*>(&sKVl[j * 72 + c * 4]) = l0;
            *reinterpret_cast<__nv_bfloat162*>(&sKVl[j * 72 + c * 4 + 2]) = l1;
        }
        __syncthreads();

        float sacc[2][4][4];
#pragma unroll
        for (int mi = 0; mi < 2; ++mi)
#pragma unroll
            for (int ni = 0; ni < 4; ++ni)
#pragma unroll
                for (int r = 0; r < 4; ++r) sacc[mi][ni][r] = 0.f;

#pragma unroll
        for (int ks = 0; ks < 4; ++ks) {
            const int ko = ks * 16;
            uint32_t ah[2][4], al[2][4];
#pragma unroll
            for (int mi = 0; mi < 2; ++mi) {
                const bf16* p = sQh + (wrow + mi * 16 + g) * 72 + ko + 2 * tig;
                ah[mi][0] = *reinterpret_cast<const uint32_t*>(p);
                ah[mi][1] = *reinterpret_cast<const uint32_t*>(p + 8 * 72);
                ah[mi][2] = *reinterpret_cast<const uint32_t*>(p + 8);
                ah[mi][3] = *reinterpret_cast<const uint32_t*>(p + 8 * 72 + 8);
                const bf16* q = sQl + (wrow + mi * 16 + g) * 72 + ko + 2 * tig;
                al[mi][0] = *reinterpret_cast<const uint32_t*>(q);
                al[mi][1] = *reinterpret_cast<const uint32_t*>(q + 8 * 72);
                al[mi][2] = *reinterpret_cast<const uint32_t*>(q + 8);
                al[mi][3] = *reinterpret_cast<const uint32_t*>(q + 8 * 72 + 8);
            }
            uint32_t bhf[4][2], blf[4][2];
#pragma unroll
            for (int ni = 0; ni < 4; ++ni) {
                const bf16* p = sKVh + (wcol + ni * 8 + g) * 72 + ko + 2 * tig;
                bhf[ni][0] = *reinterpret_cast<const uint32_t*>(p);
                bhf[ni][1] = *reinterpret_cast<const uint32_t*>(p + 8);
                const bf16* q = sKVl + (wcol + ni * 8 + g) * 72 + ko + 2 * tig;
                blf[ni][0] = *reinterpret_cast<const uint32_t*>(q);
                blf[ni][1] = *reinterpret_cast<const uint32_t*>(q + 8);
            }
#pragma unroll
            for (int mi = 0; mi < 2; ++mi)
#pragma unroll
                for (int ni = 0; ni < 4; ++ni) {
                    mma16816(sacc[mi][ni], ah[mi], bhf[ni]);
                    mma16816(sacc[mi][ni], ah[mi], blf[ni]);
                    mma16816(sacc[mi][ni], al[mi], bhf[ni]);
                }
        }

#pragma unroll
        for (int mi = 0; mi < 2; ++mi)
#pragma unroll
            for (int ni = 0; ni < 4; ++ni) {
                int col = wcol + ni * 8 + 2 * tig;
                int row = wrow + mi * 16 + g;
                sPt[col * 132 + row] = sacc[mi][ni][0];
                sPt[(col + 1) * 132 + row] = sacc[mi][ni][1];
                sPt[col * 132 + row + 8] = sacc[mi][ni][2];
                sPt[(col + 1) * 132 + row + 8] = sacc[mi][ni][3];
            }
        __syncthreads();

        if (tid < 128) {
            float tmax = -1e30f;
#pragma unroll 16
            for (int j = 0; j < 64; ++j)
                tmax = fmaxf(tmax, sPt[j * 132 + tid]);
            float m_new = fmaxf(m_run, tmax * ATTN_SCALE);
            float a = __expf(m_run - m_new);
            float sum = 0.f;
#pragma unroll 8
            for (int j2 = 0; j2 < 32; ++j2) {
                float p0 = __expf(fmaf(sPt[(2 * j2) * 132 + tid], ATTN_SCALE, -m_new));
                float p1 = __expf(fmaf(sPt[(2 * j2 + 1) * 132 + tid], ATTN_SCALE, -m_new));
                sum += p0 + p1;
                __nv_bfloat162 hh, ll;
                split2(p0, p1, hh, ll);
                sPh[tid * 36 + j2] = *reinterpret_cast<uint32_t*>(&hh);
                sPl[tid * 36 + j2] = *reinterpret_cast<uint32_t*>(&ll);
            }
            l_run = fmaf(l_run, a, sum);
            m_run = m_new;
            sAlpha[tid] = a;
        } else {
            int t2 = tid - 128;
#pragma unroll
            for (int it = 0; it < 8; ++it) {
                int id = it * 128 + t2;
                int j = id >> 4, c = id & 15;
                float4 v = *reinterpret_cast<const float4*>(
                    &Vg[(size_t)(kt + j) * HD + c * 4]);
                int d = c * 4;
                bf16 h0 = __float2bfloat16(v.x), h1 = __float2bfloat16(v.y);
                bf16 h2 = __float2bfloat16(v.z), h3 = __float2bfloat16(v.w);
                sKVh[(d + 0) * 72 + j] = h0;
                sKVh[(d + 1) * 72 + j] = h1;
                sKVh[(d + 2) * 72 + j] = h2;
                sKVh[(d + 3) * 72 + j] = h3;
                sKVl[(d + 0) * 72 + j] = __float2bfloat16(v.x - __bfloat162float(h0));
                sKVl[(d + 1) * 72 + j] = __float2bfloat16(v.y - __bfloat162float(h1));
                sKVl[(d + 2) * 72 + j] = __float2bfloat16(v.z - __bfloat162float(h2));
                sKVl[(d + 3) * 72 + j] = __float2bfloat16(v.w - __bfloat162float(h3));
            }
        }
        __syncthreads();

        {
            float a0 = sAlpha[wrow + g];
            float a1 = sAlpha[wrow + g + 8];
            float a2 = sAlpha[wrow + g + 16];
            float a3 = sAlpha[wrow + g + 24];
#pragma unroll
            for (int ni = 0; ni < 4; ++ni) {
                oacc[0][ni][0] *= a0; oacc[0][ni][1] *= a0;
                oacc[0][ni][2] *= a1; oacc[0][ni][3] *= a1;
                oacc[1][ni][0] *= a2; oacc[1][ni][1] *= a2;
                oacc[1][ni][2] *= a3; oacc[1][ni][3] *= a3;
            }
        }

#pragma unroll
        for (int ks = 0; ks < 4; ++ks) {
            uint32_t pah[2][4], pal[2][4];
#pragma unroll
            for (int mi = 0; mi < 2; ++mi) {
                int bidx = (wrow + mi * 16 + g) * 36 + ks * 8 + tig;
                pah[mi][0] = sPh[bidx];
                pah[mi][1] = sPh[bidx + 8 * 36];
                pah[mi][2] = sPh[bidx + 4];
                pah[mi][3] = sPh[bidx + 8 * 36 + 4];
                pal[mi][0] = sPl[bidx];
                pal[mi][1] = sPl[bidx + 8 * 36];
                pal[mi][2] = sPl[bidx + 4];
                pal[mi][3] = sPl[bidx + 8 * 36 + 4];
            }
            uint32_t vbh[4][2], vbl[4][2];
#pragma unroll
            for (int ni = 0; ni < 4; ++ni) {
                const bf16* p = sKVh + (wcol + ni * 8 + g) * 72 + ks * 16 + 2 * tig;
                vbh[ni][0] = *reinterpret_cast<const uint32_t*>(p);
                vbh[ni][1] = *reinterpret_cast<const uint32_t*>(p + 8);
                const bf16* q = sKVl + (wcol + ni * 8 + g) * 72 + ks * 16 + 2 * tig;
                vbl[ni][0] = *reinterpret_cast<const uint32_t*>(q);
                vbl[ni][1] = *reinterpret_cast<const uint32_t*>(q + 8);
            }
#pragma unroll
            for (int mi = 0; mi < 2; ++mi)
#pragma unroll
                for (int ni = 0; ni < 4; ++ni) {
                    mma16816(oacc[mi][ni], pah[mi], vbh[ni]);
                    mma16816(oacc[mi][ni], pah[mi], vbl[ni]);
                    mma16816(oacc[mi][ni], pal[mi], vbh[ni]);
                }
        }
        __syncthreads();
    }

    if (tid < 128) sLinv[tid] = 1.f / l_run;
    __syncthreads();

    float* Og = g_ctx + base;
#pragma unroll
    for (int mi = 0; mi < 2; ++mi) {
        int r0 = wrow + mi * 16 + g;
        float inv0 = sLinv[r0], inv1 = sLinv[r0 + 8];
#pragma unroll
        for (int ni = 0; ni < 4; ++ni) {
            int col = wcol + ni * 8 + 2 * tig;
            *reinterpret_cast<float2*>(&Og[(size_t)(qb + r0) * HD + col]) =
                make_float2(oacc[mi][ni][0] * inv0, oacc[mi][ni][1] * inv0);
            *reinterpret_cast<float2*>(&Og[(size_t)(qb + r0 + 8) * HD + col]) =
                make_float2(oacc[mi][ni][2] * inv1, oacc[mi][ni][3] * inv1);
        }
    }
}

// ---------------------------------------------------------------------------
extern "C" void kernel_launch(void* const* d_in, const int* in_sizes, int n_in,
                              void* d_out, int out_size)
{
    const float* hidden = (const float*)d_in[0];
    const float* w_qkv  = (const float*)d_in[1];
    const float* b_qkv  = (const float*)d_in[2];
    const float* w_proj = (const float*)d_in[3];
    const float* b_proj = (const float*)d_in[4];
    float* out = (float*)d_out;

    cudaFuncSetAttribute(attn_hmma,
                         cudaFuncAttributeMaxDynamicSharedMemorySize, ATTN_SMEM);

    transpose_f32<<<dim3(NQKV / 32, DMODEL / 32), dim3(32, 8)>>>(
        w_qkv, g_wqkvT, NQKV, DMODEL);
    transpose_f32<<<dim3(DMODEL / 32, DMODEL / 32), dim3(32, 8)>>>(
        w_proj, g_wprojT, DMODEL, DMODEL);

    qkv_gemm_hmma<<<dim3(NQKV / 128, MTOT / 128), 256>>>(
        hidden, g_wqkvT, b_qkv);
    attn_hmma<<<dim3(SEQ / 128, NH, BATCH), 256, ATTN_SMEM>>>();
    proj_gemm_hmma<<<dim3(DMODEL / 128, MTOT / 128), 256>>>(
        g_wprojT, b_proj, out);
}

// round 13
// speedup vs baseline: 1.0094x; 1.0094x over previous
#include <cuda_runtime.h>
#include <cuda_bf16.h>
#include <math.h>
#include <stdint.h>

#define BATCH 8
#define SEQ 1024
#define DMODEL 768
#define NH 12
#define HD 64
#define ATTN_SCALE 0.125f
#define MTOT (BATCH * SEQ)         /* 8192 */
#define NQKV (3 * DMODEL)          /* 2304 */

typedef __nv_bfloat16 bf16;

// ---------------------------------------------------------------------------
// Scratch — fp32 only (proven-safe static layout)
// ---------------------------------------------------------------------------
__device__ float g_q[BATCH * NH * SEQ * HD];
__device__ float g_k[BATCH * NH * SEQ * HD];
__device__ float g_v[BATCH * NH * SEQ * HD];
__device__ float g_ctx[BATCH * NH * SEQ * HD];
__device__ float g_wqkvT[NQKV * DMODEL];      // [N][K] fp32
__device__ float g_wprojT[DMODEL * DMODEL];   // [N][K] fp32

// ---------------------------------------------------------------------------
// HMMA helper (m16n8k16, bf16 in / fp32 accumulate)
// ---------------------------------------------------------------------------
__device__ __forceinline__ void mma16816(float* c, const uint32_t* a,
                                         const uint32_t* b) {
    asm volatile(
        "mma.sync.aligned.m16n8k16.row.col.f32.bf16.bf16.f32 "
        "{%0,%1,%2,%3}, {%4,%5,%6,%7}, {%8,%9}, {%0,%1,%2,%3};"
        : "+f"(c[0]), "+f"(c[1]), "+f"(c[2]), "+f"(c[3])
        : "r"(a[0]), "r"(a[1]), "r"(a[2]), "r"(a[3]), "r"(b[0]), "r"(b[1]));
}

__device__ __forceinline__ void split2(float v0, float v1,
                                       __nv_bfloat162& h, __nv_bfloat162& l) {
    bf16 h0 = __float2bfloat16(v0), h1 = __float2bfloat16(v1);
    h = __halves2bfloat162(h0, h1);
    l = __halves2bfloat162(__float2bfloat16(v0 - __bfloat162float(h0)),
                           __float2bfloat16(v1 - __bfloat162float(h1)));
}

// ---------------------------------------------------------------------------
// fp32 transpose: W [K][N] -> WT [N][K]  (R10/R12-proven)
// ---------------------------------------------------------------------------
__global__ void transpose_f32(const float* __restrict__ W,
                              float* __restrict__ WT, int N, int K)
{
    __shared__ float t[32][33];
    int n0 = blockIdx.x * 32, k0 = blockIdx.y * 32;
    int tx = threadIdx.x, ty = threadIdx.y;
#pragma unroll
    for (int i = 0; i < 4; ++i)
        t[ty + i * 8][tx] = W[(size_t)(k0 + ty + i * 8) * N + n0 + tx];
    __syncthreads();
#pragma unroll
    for (int i = 0; i < 4; ++i) {
        int n = ty + i * 8;
        WT[(size_t)(n0 + n) * K + k0 + tx] = t[tx][n];
    }
}

// ---------------------------------------------------------------------------
// Shared HMMA compute for one staged 32-k chunk (bf16 hi/lo smem, stride 40).
// ---------------------------------------------------------------------------
__device__ __forceinline__ void hmma_chunk(
    const bf16* sAh, const bf16* sAl, const bf16* sBh, const bf16* sBl,
    int wrow, int wcol, int g, int tig, float acc[2][8][4])
{
#pragma unroll
    for (int ks = 0; ks < 2; ++ks) {
        const int ko = ks * 16;
        uint32_t ah[2][4], al[2][4];
#pragma unroll
        for (int mi = 0; mi < 2; ++mi) {
            const bf16* p = sAh + (wrow + mi * 16 + g) * 40 + ko + 2 * tig;
            ah[mi][0] = *reinterpret_cast<const uint32_t*>(p);
            ah[mi][1] = *reinterpret_cast<const uint32_t*>(p + 8 * 40);
            ah[mi][2] = *reinterpret_cast<const uint32_t*>(p + 8);
            ah[mi][3] = *reinterpret_cast<const uint32_t*>(p + 8 * 40 + 8);
            const bf16* q = sAl + (wrow + mi * 16 + g) * 40 + ko + 2 * tig;
            al[mi][0] = *reinterpret_cast<const uint32_t*>(q);
            al[mi][1] = *reinterpret_cast<const uint32_t*>(q + 8 * 40);
            al[mi][2] = *reinterpret_cast<const uint32_t*>(q + 8);
            al[mi][3] = *reinterpret_cast<const uint32_t*>(q + 8 * 40 + 8);
        }
        uint32_t bhf[8][2], blf[8][2];
#pragma unroll
        for (int ni = 0; ni < 8; ++ni) {
            const bf16* p = sBh + (wcol + ni * 8 + g) * 40 + ko + 2 * tig;
            bhf[ni][0] = *reinterpret_cast<const uint32_t*>(p);
            bhf[ni][1] = *reinterpret_cast<const uint32_t*>(p + 8);
            const bf16* q = sBl + (wcol + ni * 8 + g) * 40 + ko + 2 * tig;
            blf[ni][0] = *reinterpret_cast<const uint32_t*>(q);
            blf[ni][1] = *reinterpret_cast<const uint32_t*>(q + 8);
        }
#pragma unroll
        for (int mi = 0; mi < 2; ++mi)
#pragma unroll
            for (int ni = 0; ni < 8; ++ni) {
                mma16816(acc[mi][ni], ah[mi], bhf[ni]);
                mma16816(acc[mi][ni], ah[mi], blf[ni]);
                mma16816(acc[mi][ni], al[mi], bhf[ni]);
            }
    }
}

// Stage one [128 rows][32 k] fp32 source tile into split bf16 smem (stride 40)
// Contiguous-in-k source rows; vectorized 8B stores, conflict-free.
__device__ __forceinline__ void stage_rows(
    bf16* sh, bf16* sl, const float* __restrict__ G, int rowstride,
    int rowbase, int kt, int tid)
{
#pragma unroll
    for (int it = 0; it < 4; ++it) {
        int id = it * 256 + tid;
        int row = id >> 3, c = id & 7;
        float4 v = *reinterpret_cast<const float4*>(
            &G[(size_t)(rowbase + row) * rowstride + kt + c * 4]);
        __nv_bfloat162 h0, l0, h1, l1;
        split2(v.x, v.y, h0, l0);
        split2(v.z, v.w, h1, l1);
        int o = row * 40 + c * 4;
        *reinterpret_cast<__nv_bfloat162*>(&sh[o]) = h0;
        *reinterpret_cast<__nv_bfloat162*>(&sh[o + 2]) = h1;
        *reinterpret_cast<__nv_bfloat162*>(&sl[o]) = l0;
        *reinterpret_cast<__nv_bfloat162*>(&sl[o + 2]) = l1;
    }
}

// ---------------------------------------------------------------------------
// QKV GEMM: HMMA, both operands contiguous [row][k]; natural occupancy.
// ---------------------------------------------------------------------------
__global__ __launch_bounds__(256) void qkv_gemm_hmma(
    const float* __restrict__ A, const float* __restrict__ BT,
    const float* __restrict__ bias)
{
    __shared__ bf16 smem[512 * 40];          // 40960 B
    bf16* sAh = smem;
    bf16* sAl = smem + 128 * 40;
    bf16* sBh = smem + 256 * 40;
    bf16* sBl = smem + 384 * 40;

    const int tid = threadIdx.x;
    const int wid = tid >> 5, lane = tid & 31;
    const int nb = blockIdx.x * 128, mb = blockIdx.y * 128;
    const int wrow = (wid & 3) * 32;
    const int wcol = (wid >> 2) * 64;
    const int g = lane >> 2, tig = lane & 3;

    float acc[2][8][4];
#pragma unroll
    for (int mi = 0; mi < 2; ++mi)
#pragma unroll
        for (int ni = 0; ni < 8; ++ni)
#pragma unroll
            for (int r = 0; r < 4; ++r) acc[mi][ni][r] = 0.f;

#pragma unroll 1
    for (int i = 0; i < 24; ++i) {
        stage_rows(sAh, sAl, A, DMODEL, mb, i * 32, tid);
        stage_rows(sBh, sBl, BT, DMODEL, nb, i * 32, tid);
        __syncthreads();
        hmma_chunk(sAh, sAl, sBh, sBl, wrow, wcol, g, tig, acc);
        __syncthreads();
    }

    // Epilogue: scatter fp32 into g_q/g_k/g_v [B,H,S,HD] + bias
#pragma unroll
    for (int mi = 0; mi < 2; ++mi)
#pragma unroll
        for (int ni = 0; ni < 8; ++ni) {
            int col = nb + wcol + ni * 8 + 2 * tig;
            int which = col / DMODEL;
            int rem = col - which * DMODEL;
            int h = rem >> 6, d = rem & 63;
            float* dst = (which == 0) ? g_q : ((which == 1) ? g_k : g_v);
            float b0 = bias[col], b1 = bias[col + 1];
#pragma unroll
            for (int half = 0; half < 2; ++half) {
                int m = mb + wrow + mi * 16 + g + half * 8;
                int bb = m >> 10, s = m & 1023;
                float2 o = make_float2(acc[mi][ni][half * 2 + 0] + b0,
                                       acc[mi][ni][half * 2 + 1] + b1);
                *reinterpret_cast<float2*>(
                    &dst[(((size_t)(bb * NH + h) * SEQ + s) * HD) + d]) = o;
            }
        }
}

// ---------------------------------------------------------------------------
// Proj GEMM: A gathered from g_ctx [B,H,S,HD], B = g_wprojT; natural occupancy.
// ---------------------------------------------------------------------------
__global__ __launch_bounds__(256) void proj_gemm_hmma(
    const float* __restrict__ BT, const float* __restrict__ bias,
    float* __restrict__ out)
{
    __shared__ bf16 smem[512 * 40];
    bf16* sAh = smem;
    bf16* sAl = smem + 128 * 40;
    bf16* sBh = smem + 256 * 40;
    bf16* sBl = smem + 384 * 40;

    const int tid = threadIdx.x;
    const int wid = tid >> 5, lane = tid & 31;
    const int nb = blockIdx.x * 128, mb = blockIdx.y * 128;
    const int wrow = (wid & 3) * 32;
    const int wcol = (wid >> 2) * 64;
    const int g = lane >> 2, tig = lane & 3;

    float acc[2][8][4];
#pragma unroll
    for (int mi = 0; mi < 2; ++mi)
#pragma unroll
        for (int ni = 0; ni < 8; ++ni)
#pragma unroll
            for (int r = 0; r < 4; ++r) acc[mi][ni][r] = 0.f;

#pragma unroll 1
    for (int i = 0; i < 24; ++i) {
        int kt = i * 32;
        // A: gather from g_ctx (chunk never crosses a head boundary)
#pragma unroll
        for (int it = 0; it < 4; ++it) {
            int id = it * 256 + tid;
            int row = id >> 3, c = id & 7;
            int m = mb + row;
            int bb = m >> 10, s = m & 1023;
            int kg = kt + c * 4;
            int hk = kg >> 6, d = kg & 63;
            float4 v = *reinterpret_cast<const float4*>(
                &g_ctx[(((size_t)(bb * NH + hk) * SEQ + s) * HD) + d]);
            __nv_bfloat162 h0, l0, h1, l1;
            split2(v.x, v.y, h0, l0);
            split2(v.z, v.w, h1, l1);
            int o = row * 40 + c * 4;
            *reinterpret_cast<__nv_bfloat162*>(&sAh[o]) = h0;
            *reinterpret_cast<__nv_bfloat162*>(&sAh[o + 2]) = h1;
            *reinterpret_cast<__nv_bfloat162*>(&sAl[o]) = l0;
            *reinterpret_cast<__nv_bfloat162*>(&sAl[o + 2]) = l1;
        }
        stage_rows(sBh, sBl, BT, DMODEL, nb, kt, tid);
        __syncthreads();
        hmma_chunk(sAh, sAl, sBh, sBl, wrow, wcol, g, tig, acc);
        __syncthreads();
    }

#pragma unroll
    for (int mi = 0; mi < 2; ++mi)
#pragma unroll
        for (int ni = 0; ni < 8; ++ni) {
            int col = nb + wcol + ni * 8 + 2 * tig;
            float b0 = bias[col], b1 = bias[col + 1];
#pragma unroll
            for (int half = 0; half < 2; ++half) {
                int row = mb + wrow + mi * 16 + g + half * 8;
                float2 o = make_float2(acc[mi][ni][half * 2 + 0] + b0,
                                       acc[mi][ni][half * 2 + 1] + b1);
                *reinterpret_cast<float2*>(&out[(size_t)row * DMODEL + col]) = o;
            }
        }
}

// ---------------------------------------------------------------------------
// Flash attention via HMMA (byte-identical to passing R9/R11 kernel)
// ---------------------------------------------------------------------------
#define ATTN_SMEM 126976

__global__ __launch_bounds__(256) void attn_hmma()
{
    extern __shared__ char sm[];
    bf16* sQh = (bf16*)(sm + 0);
    bf16* sQl = (bf16*)(sm + 18432);
    bf16* sKVh = (bf16*)(sm + 36864);
    bf16* sKVl = (bf16*)(sm + 46080);
    float* sPt = (float*)(sm + 55296);
    uint32_t* sPh = (uint32_t*)(sm + 89088);
    uint32_t* sPl = (uint32_t*)(sm + 107520);
    float* sAlpha = (float*)(sm + 125952);
    float* sLinv = (float*)(sm + 126464);

    const int tid = threadIdx.x;
    const int wid = tid >> 5, lane = tid & 31;
    const int qb = blockIdx.x * 128;
    const int h = blockIdx.y, b = blockIdx.z;
    const size_t base = ((size_t)(b * NH + h)) * SEQ * HD;
    const float* Qg = g_q + base;
    const float* Kg = g_k + base;
    const float* Vg = g_v + base;

    const int wrow = (wid & 3) * 32;
    const int wcol = (wid >> 2) * 32;
    const int g = lane >> 2, tig = lane & 3;

#pragma unroll
    for (int it = 0; it < 8; ++it) {
        int id = it * 256 + tid;
        int row = id >> 4, c = id & 15;
        float4 v = *reinterpret_cast<const float4*>(
            &Qg[(size_t)(qb + row) * HD + c * 4]);
        __nv_bfloat162 h0, l0, h1, l1;
        split2(v.x, v.y, h0, l0);
        split2(v.z, v.w, h1, l1);
        *reinterpret_cast<__nv_bfloat162*>(&sQh[row * 72 + c * 4]) = h0;
        *reinterpret_cast<__nv_bfloat162*>(&sQh[row * 72 + c * 4 + 2]) = h1;
        *reinterpret_cast<__nv_bfloat162*>(&sQl[row * 72 + c * 4]) = l0;
        *reinterpret_cast<__nv_bfloat162*>(&sQl[row * 72 + c * 4 + 2]) = l1;
    }

    float oacc[2][4][4];
#pragma unroll
    for (int mi = 0; mi < 2; ++mi)
#pragma unroll
        for (int ni = 0; ni < 4; ++ni)
#pragma unroll
            for (int r = 0; r < 4; ++r) oacc[mi][ni][r] = 0.f;
    float m_run = -1e30f, l_run = 0.f;

    for (int kt = 0; kt < SEQ; kt += 64) {
#pragma unroll
        for (int it = 0; it < 4; ++it) {
            int id = it * 256 + tid;
            int j = id >> 4, c = id & 15;
            float4 v = *reinterpret_cast<const float4*>(
                &Kg[(size_t)(kt + j) * HD + c * 4]);
            __nv_bfloat162 h0, l0, h1, l1;
            split2(v.x, v.y, h0, l0);
            split2(v.z, v.w, h1, l1);
            *reinterpret_cast<__nv_bfloat162*>(&sKVh[j * 72 + c * 4]) = h0;
            *reinterpret_cast<__nv_bfloat162*>(&sKVh[j * 72 + c * 4 + 2]) = h1;
            *reinterpret_cast<__nv_bfloat162*>(&sKVl[j * 72 + c * 4]) = l0;
            *reinterpret_cast<__nv_bfloat162*>(&sKVl[j * 72 + c * 4 + 2]) = l1;
        }
        __syncthreads();

        float sacc[2][4][4];
#pragma unroll
        for (int mi = 0; mi < 2; ++mi)
#pragma unroll
            for (int ni = 0; ni < 4; ++ni)
#pragma unroll
                for (int r = 0; r < 4; ++r) sacc[mi][ni][r] = 0.f;

#pragma unroll
        for (int ks = 0; ks < 4; ++ks) {
            const int ko = ks * 16;
            uint32_t ah[2][4], al[2][4];
#pragma unroll
            for (int mi = 0; mi < 2; ++mi) {
                const bf16* p = sQh + (wrow + mi * 16 + g) * 72 + ko + 2 * tig;
                ah[mi][0] = *reinterpret_cast<const uint32_t*>(p);
                ah[mi][1] = *reinterpret_cast<const uint32_t*>(p + 8 * 72);
                ah[mi][2] = *reinterpret_cast<const uint32_t*>(p + 8);
                ah[mi][3] = *reinterpret_cast<const uint32_t*>(p + 8 * 72 + 8);
                const bf16* q = sQl + (wrow + mi * 16 + g) * 72 + ko + 2 * tig;
                al[mi][0] = *reinterpret_cast<const uint32_t*>(q);
                al[mi][1] = *reinterpret_cast<const uint32_t*>(q + 8 * 72);
                al[mi][2] = *reinterpret_cast<const uint32_t*>(q + 8);
                al[mi][3] = *reinterpret_cast<const uint32_t*>(q + 8 * 72 + 8);
            }
            uint32_t bhf[4][2], blf[4][2];
#pragma unroll
            for (int ni = 0; ni < 4; ++ni) {
                const bf16* p = sKVh + (wcol + ni * 8 + g) * 72 + ko + 2 * tig;
                bhf[ni][0] = *reinterpret_cast<const uint32_t*>(p);
                bhf[ni][1] = *reinterpret_cast<const uint32_t*>(p + 8);
                const bf16* q = sKVl + (wcol + ni * 8 + g) * 72 + ko + 2 * tig;
                blf[ni][0] = *reinterpret_cast<const uint32_t*>(q);
                blf[ni][1] = *reinterpret_cast<const uint32_t*>(q + 8);
            }
#pragma unroll
            for (int mi = 0; mi < 2; ++mi)
#pragma unroll
                for (int ni = 0; ni < 4; ++ni) {
                    mma16816(sacc[mi][ni], ah[mi], bhf[ni]);
                    mma16816(sacc[mi][ni], ah[mi], blf[ni]);
                    mma16816(sacc[mi][ni], al[mi], bhf[ni]);
                }
        }

#pragma unroll
        for (int mi = 0; mi < 2; ++mi)
#pragma unroll
            for (int ni = 0; ni < 4; ++ni) {
                int col = wcol + ni * 8 + 2 * tig;
                int row = wrow + mi * 16 + g;
                sPt[col * 132 + row] = sacc[mi][ni][0];
                sPt[(col + 1) * 132 + row] = sacc[mi][ni][1];
                sPt[col * 132 + row + 8] = sacc[mi][ni][2];
                sPt[(col + 1) * 132 + row + 8] = sacc[mi][ni][3];
            }
        __syncthreads();

        if (tid < 128) {
            float tmax = -1e30f;
#pragma unroll 16
            for (int j = 0; j < 64; ++j)
                tmax = fmaxf(tmax, sPt[j * 132 + tid]);
            float m_new = fmaxf(m_run, tmax * ATTN_SCALE);
            float a = __expf(m_run - m_new);
            float sum = 0.f;
#pragma unroll 8
            for (int j2 = 0; j2 < 32; ++j2) {
                float p0 = __expf(fmaf(sPt[(2 * j2) * 132 + tid], ATTN_SCALE, -m_new));
                float p1 = __expf(fmaf(sPt[(2 * j2 + 1) * 132 + tid], ATTN_SCALE, -m_new));
                sum += p0 + p1;
                __nv_bfloat162 hh, ll;
                split2(p0, p1, hh, ll);
                sPh[tid * 36 + j2] = *reinterpret_cast<uint32_t*>(&hh);
                sPl[tid * 36 + j2] = *reinterpret_cast<uint32_t*>(&ll);
            }
            l_run = fmaf(l_run, a, sum);
            m_run = m_new;
            sAlpha[tid] = a;
        } else {
            int t2 = tid - 128;
#pragma unroll
            for (int it = 0; it < 8; ++it) {
                int id = it * 128 + t2;
                int j = id >> 4, c = id & 15;
                float4 v = *reinterpret_cast<const float4*>(
                    &Vg[(size_t)(kt + j) * HD + c * 4]);
                int d = c * 4;
                bf16 h0 = __float2bfloat16(v.x), h1 = __float2bfloat16(v.y);
                bf16 h2 = __float2bfloat16(v.z), h3 = __float2bfloat16(v.w);
                sKVh[(d + 0) * 72 + j] = h0;
                sKVh[(d + 1) * 72 + j] = h1;
                sKVh[(d + 2) * 72 + j] = h2;
                sKVh[(d + 3) * 72 + j] = h3;
                sKVl[(d + 0) * 72 + j] = __float2bfloat16(v.x - __bfloat162float(h0));
                sKVl[(d + 1) * 72 + j] = __float2bfloat16(v.y - __bfloat162float(h1));
                sKVl[(d + 2) * 72 + j] = __float2bfloat16(v.z - __bfloat162float(h2));
                sKVl[(d + 3) * 72 + j] = __float2bfloat16(v.w - __bfloat162float(h3));
            }
        }
        __syncthreads();

        {
            float a0 = sAlpha[wrow + g];
            float a1 = sAlpha[wrow + g + 8];
            float a2 = sAlpha[wrow + g + 16];
            float a3 = sAlpha[wrow + g + 24];
#pragma unroll
            for (int ni = 0; ni < 4; ++ni) {
                oacc[0][ni][0] *= a0; oacc[0][ni][1] *= a0;
                oacc[0][ni][2] *= a1; oacc[0][ni][3] *= a1;
                oacc[1][ni][0] *= a2; oacc[1][ni][1] *= a2;
                oacc[1][ni][2] *= a3; oacc[1][ni][3] *= a3;
            }
        }

#pragma unroll
        for (int ks = 0; ks < 4; ++ks) {
            uint32_t pah[2][4], pal[2][4];
#pragma unroll
            for (int mi = 0; mi < 2; ++mi) {
                int bidx = (wrow + mi * 16 + g) * 36 + ks * 8 + tig;
                pah[mi][0] = sPh[bidx];
                pah[mi][1] = sPh[bidx + 8 * 36];
                pah[mi][2] = sPh[bidx + 4];
                pah[mi][3] = sPh[bidx + 8 * 36 + 4];
                pal[mi][0] = sPl[bidx];
                pal[mi][1] = sPl[bidx + 8 * 36];
                pal[mi][2] = sPl[bidx + 4];
                pal[mi][3] = sPl[bidx + 8 * 36 + 4];
            }
            uint32_t vbh[4][2], vbl[4][2];
#pragma unroll
            for (int ni = 0; ni < 4; ++ni) {
                const bf16* p = sKVh + (wcol + ni * 8 + g) * 72 + ks * 16 + 2 * tig;
                vbh[ni][0] = *reinterpret_cast<const uint32_t*>(p);
                vbh[ni][1] = *reinterpret_cast<const uint32_t*>(p + 8);
                const bf16* q = sKVl + (wcol + ni * 8 + g) * 72 + ks * 16 + 2 * tig;
                vbl[ni][0] = *reinterpret_cast<const uint32_t*>(q);
                vbl[ni][1] = *reinterpret_cast<const uint32_t*>(q + 8);
            }
#pragma unroll
            for (int mi = 0; mi < 2; ++mi)
#pragma unroll
                for (int ni = 0; ni < 4; ++ni) {
                    mma16816(oacc[mi][ni], pah[mi], vbh[ni]);
                    mma16816(oacc[mi][ni], pah[mi], vbl[ni]);
                    mma16816(oacc[mi][ni], pal[mi], vbh[ni]);
                }
        }
        __syncthreads();
    }

    if (tid < 128) sLinv[tid] = 1.f / l_run;
    __syncthreads();

    float* Og = g_ctx + base;
#pragma unroll
    for (int mi = 0; mi < 2; ++mi) {
        int r0 = wrow + mi * 16 + g;
        float inv0 = sLinv[r0], inv1 = sLinv[r0 + 8];
#pragma unroll
        for (int ni = 0; ni < 4; ++ni) {
            int col = wcol + ni * 8 + 2 * tig;
            *reinterpret_cast<float2*>(&Og[(size_t)(qb + r0) * HD + col]) =
                make_float2(oacc[mi][ni][0] * inv0, oacc[mi][ni][1] * inv0);
            *reinterpret_cast<float2*>(&Og[(size_t)(qb + r0 + 8) * HD + col]) =
                make_float2(oacc[mi][ni][2] * inv1, oacc[mi][ni][3] * inv1);
        }
    }
}

// ---------------------------------------------------------------------------
extern "C" void kernel_launch(void* const* d_in, const int* in_sizes, int n_in,
                              void* d_out, int out_size)
{
    const float* hidden = (const float*)d_in[0];
    const float* w_qkv  = (const float*)d_in[1];
    const float* b_qkv  = (const float*)d_in[2];
    const float* w_proj = (const float*)d_in[3];
    const float* b_proj = (const float*)d_in[4];
    float* out = (float*)d_out;

    cudaFuncSetAttribute(attn_hmma,
                         cudaFuncAttributeMaxDynamicSharedMemorySize, ATTN_SMEM);

    transpose_f32<<<dim3(NQKV / 32, DMODEL / 32), dim3(32, 8)>>>(
        w_qkv, g_wqkvT, NQKV, DMODEL);
    transpose_f32<<<dim3(DMODEL / 32, DMODEL / 32), dim3(32, 8)>>>(
        w_proj, g_wprojT, DMODEL, DMODEL);

    qkv_gemm_hmma<<<dim3(NQKV / 128, MTOT / 128), 256>>>(
        hidden, g_wqkvT, b_qkv);
    attn_hmma<<<dim3(SEQ / 128, NH, BATCH), 256, ATTN_SMEM>>>();
    proj_gemm_hmma<<<dim3(DMODEL / 128, MTOT / 128), 256>>>(
        g_wprojT, b_proj, out);
}

// round 14
// speedup vs baseline: 4.0012x; 3.9638x over previous
#include <cuda_runtime.h>
#include <cuda_bf16.h>
#include <math.h>
#include <stdint.h>

#define BATCH 8
#define SEQ 1024
#define DMODEL 768
#define NH 12
#define HD 64
#define ATTN_SCALE 0.125f
#define MTOT (BATCH * SEQ)         /* 8192 */
#define NQKV (3 * DMODEL)          /* 2304 */

typedef __nv_bfloat16 bf16;

// ---------------------------------------------------------------------------
// Scratch — fp32 only; accessed ONLY from device code (never as host-side
// kernel args: on GB300 the host-shadow address is ATS-dereferenceable and
// silently routes through NVLink-C2C host memory).
// ---------------------------------------------------------------------------
__device__ float g_q[BATCH * NH * SEQ * HD];
__device__ float g_k[BATCH * NH * SEQ * HD];
__device__ float g_v[BATCH * NH * SEQ * HD];
__device__ float g_ctx[BATCH * NH * SEQ * HD];
__device__ float g_wqkvT[NQKV * DMODEL];      // [N][K] fp32
__device__ float g_wprojT[DMODEL * DMODEL];   // [N][K] fp32

// ---------------------------------------------------------------------------
// HMMA helper (m16n8k16, bf16 in / fp32 accumulate)
// ---------------------------------------------------------------------------
__device__ __forceinline__ void mma16816(float* c, const uint32_t* a,
                                         const uint32_t* b) {
    asm volatile(
        "mma.sync.aligned.m16n8k16.row.col.f32.bf16.bf16.f32 "
        "{%0,%1,%2,%3}, {%4,%5,%6,%7}, {%8,%9}, {%0,%1,%2,%3};"
        : "+f"(c[0]), "+f"(c[1]), "+f"(c[2]), "+f"(c[3])
        : "r"(a[0]), "r"(a[1]), "r"(a[2]), "r"(a[3]), "r"(b[0]), "r"(b[1]));
}

__device__ __forceinline__ void split2(float v0, float v1,
                                       __nv_bfloat162& h, __nv_bfloat162& l) {
    bf16 h0 = __float2bfloat16(v0), h1 = __float2bfloat16(v1);
    h = __halves2bfloat162(h0, h1);
    l = __halves2bfloat162(__float2bfloat16(v0 - __bfloat162float(h0)),
                           __float2bfloat16(v1 - __bfloat162float(h1)));
}

// ---------------------------------------------------------------------------
// fp32 transposes: W [K][N] -> WT [N][K], destination fixed per kernel so the
// __device__ global is referenced in device code only.
// ---------------------------------------------------------------------------
__device__ __forceinline__ void transpose_body(
    const float* __restrict__ W, float* __restrict__ WT, int N, int K)
{
    __shared__ float t[32][33];
    int n0 = blockIdx.x * 32, k0 = blockIdx.y * 32;
    int tx = threadIdx.x, ty = threadIdx.y;
#pragma unroll
    for (int i = 0; i < 4; ++i)
        t[ty + i * 8][tx] = W[(size_t)(k0 + ty + i * 8) * N + n0 + tx];
    __syncthreads();
#pragma unroll
    for (int i = 0; i < 4; ++i) {
        int n = ty + i * 8;
        WT[(size_t)(n0 + n) * K + k0 + tx] = t[tx][n];
    }
}

__global__ void transpose_wqkv(const float* __restrict__ W)
{
    transpose_body(W, g_wqkvT, NQKV, DMODEL);
}

__global__ void transpose_wproj(const float* __restrict__ W)
{
    transpose_body(W, g_wprojT, DMODEL, DMODEL);
}

// ---------------------------------------------------------------------------
// Shared HMMA compute for one staged 32-k chunk (bf16 hi/lo smem, stride 40).
// ---------------------------------------------------------------------------
__device__ __forceinline__ void hmma_chunk(
    const bf16* sAh, const bf16* sAl, const bf16* sBh, const bf16* sBl,
    int wrow, int wcol, int g, int tig, float acc[2][8][4])
{
#pragma unroll
    for (int ks = 0; ks < 2; ++ks) {
        const int ko = ks * 16;
        uint32_t ah[2][4], al[2][4];
#pragma unroll
        for (int mi = 0; mi < 2; ++mi) {
            const bf16* p = sAh + (wrow + mi * 16 + g) * 40 + ko + 2 * tig;
            ah[mi][0] = *reinterpret_cast<const uint32_t*>(p);
            ah[mi][1] = *reinterpret_cast<const uint32_t*>(p + 8 * 40);
            ah[mi][2] = *reinterpret_cast<const uint32_t*>(p + 8);
            ah[mi][3] = *reinterpret_cast<const uint32_t*>(p + 8 * 40 + 8);
            const bf16* q = sAl + (wrow + mi * 16 + g) * 40 + ko + 2 * tig;
            al[mi][0] = *reinterpret_cast<const uint32_t*>(q);
            al[mi][1] = *reinterpret_cast<const uint32_t*>(q + 8 * 40);
            al[mi][2] = *reinterpret_cast<const uint32_t*>(q + 8);
            al[mi][3] = *reinterpret_cast<const uint32_t*>(q + 8 * 40 + 8);
        }
        uint32_t bhf[8][2], blf[8][2];
#pragma unroll
        for (int ni = 0; ni < 8; ++ni) {
            const bf16* p = sBh + (wcol + ni * 8 + g) * 40 + ko + 2 * tig;
            bhf[ni][0] = *reinterpret_cast<const uint32_t*>(p);
            bhf[ni][1] = *reinterpret_cast<const uint32_t*>(p + 8);
            const bf16* q = sBl + (wcol + ni * 8 + g) * 40 + ko + 2 * tig;
            blf[ni][0] = *reinterpret_cast<const uint32_t*>(q);
            blf[ni][1] = *reinterpret_cast<const uint32_t*>(q + 8);
        }
#pragma unroll
        for (int mi = 0; mi < 2; ++mi)
#pragma unroll
            for (int ni = 0; ni < 8; ++ni) {
                mma16816(acc[mi][ni], ah[mi], bhf[ni]);
                mma16816(acc[mi][ni], ah[mi], blf[ni]);
                mma16816(acc[mi][ni], al[mi], bhf[ni]);
            }
    }
}

// Stage one [128 rows][32 k] fp32 source tile into split bf16 smem (stride 40)
// Contiguous-in-k source rows; vectorized 8B stores, conflict-free.
__device__ __forceinline__ void stage_rows(
    bf16* sh, bf16* sl, const float* __restrict__ G, int rowstride,
    int rowbase, int kt, int tid)
{
#pragma unroll
    for (int it = 0; it < 4; ++it) {
        int id = it * 256 + tid;
        int row = id >> 3, c = id & 7;
        float4 v = *reinterpret_cast<const float4*>(
            &G[(size_t)(rowbase + row) * rowstride + kt + c * 4]);
        __nv_bfloat162 h0, l0, h1, l1;
        split2(v.x, v.y, h0, l0);
        split2(v.z, v.w, h1, l1);
        int o = row * 40 + c * 4;
        *reinterpret_cast<__nv_bfloat162*>(&sh[o]) = h0;
        *reinterpret_cast<__nv_bfloat162*>(&sh[o + 2]) = h1;
        *reinterpret_cast<__nv_bfloat162*>(&sl[o]) = l0;
        *reinterpret_cast<__nv_bfloat162*>(&sl[o + 2]) = l1;
    }
}

// ---------------------------------------------------------------------------
// QKV GEMM: HMMA, both operands contiguous [row][k]; weights from device
// global g_wqkvT (device-side reference).
// ---------------------------------------------------------------------------
__global__ __launch_bounds__(256) void qkv_gemm_hmma(
    const float* __restrict__ A, const float* __restrict__ bias)
{
    __shared__ bf16 smem[512 * 40];          // 40960 B
    bf16* sAh = smem;
    bf16* sAl = smem + 128 * 40;
    bf16* sBh = smem + 256 * 40;
    bf16* sBl = smem + 384 * 40;

    const float* BT = g_wqkvT;               // device-side address

    const int tid = threadIdx.x;
    const int wid = tid >> 5, lane = tid & 31;
    const int nb = blockIdx.x * 128, mb = blockIdx.y * 128;
    const int wrow = (wid & 3) * 32;
    const int wcol = (wid >> 2) * 64;
    const int g = lane >> 2, tig = lane & 3;

    float acc[2][8][4];
#pragma unroll
    for (int mi = 0; mi < 2; ++mi)
#pragma unroll
        for (int ni = 0; ni < 8; ++ni)
#pragma unroll
            for (int r = 0; r < 4; ++r) acc[mi][ni][r] = 0.f;

#pragma unroll 1
    for (int i = 0; i < 24; ++i) {
        stage_rows(sAh, sAl, A, DMODEL, mb, i * 32, tid);
        stage_rows(sBh, sBl, BT, DMODEL, nb, i * 32, tid);
        __syncthreads();
        hmma_chunk(sAh, sAl, sBh, sBl, wrow, wcol, g, tig, acc);
        __syncthreads();
    }

    // Epilogue: scatter fp32 into g_q/g_k/g_v [B,H,S,HD] + bias
#pragma unroll
    for (int mi = 0; mi < 2; ++mi)
#pragma unroll
        for (int ni = 0; ni < 8; ++ni) {
            int col = nb + wcol + ni * 8 + 2 * tig;
            int which = col / DMODEL;
            int rem = col - which * DMODEL;
            int h = rem >> 6, d = rem & 63;
            float* dst = (which == 0) ? g_q : ((which == 1) ? g_k : g_v);
            float b0 = bias[col], b1 = bias[col + 1];
#pragma unroll
            for (int half = 0; half < 2; ++half) {
                int m = mb + wrow + mi * 16 + g + half * 8;
                int bb = m >> 10, s = m & 1023;
                float2 o = make_float2(acc[mi][ni][half * 2 + 0] + b0,
                                       acc[mi][ni][half * 2 + 1] + b1);
                *reinterpret_cast<float2*>(
                    &dst[(((size_t)(bb * NH + h) * SEQ + s) * HD) + d]) = o;
            }
        }
}

// ---------------------------------------------------------------------------
// Proj GEMM: A gathered from g_ctx, weights from device global g_wprojT.
// ---------------------------------------------------------------------------
__global__ __launch_bounds__(256) void proj_gemm_hmma(
    const float* __restrict__ bias, float* __restrict__ out)
{
    __shared__ bf16 smem[512 * 40];
    bf16* sAh = smem;
    bf16* sAl = smem + 128 * 40;
    bf16* sBh = smem + 256 * 40;
    bf16* sBl = smem + 384 * 40;

    const float* BT = g_wprojT;              // device-side address

    const int tid = threadIdx.x;
    const int wid = tid >> 5, lane = tid & 31;
    const int nb = blockIdx.x * 128, mb = blockIdx.y * 128;
    const int wrow = (wid & 3) * 32;
    const int wcol = (wid >> 2) * 64;
    const int g = lane >> 2, tig = lane & 3;

    float acc[2][8][4];
#pragma unroll
    for (int mi = 0; mi < 2; ++mi)
#pragma unroll
        for (int ni = 0; ni < 8; ++ni)
#pragma unroll
            for (int r = 0; r < 4; ++r) acc[mi][ni][r] = 0.f;

#pragma unroll 1
    for (int i = 0; i < 24; ++i) {
        int kt = i * 32;
        // A: gather from g_ctx (chunk never crosses a head boundary)
#pragma unroll
        for (int it = 0; it < 4; ++it) {
            int id = it * 256 + tid;
            int row = id >> 3, c = id & 7;
            int m = mb + row;
            int bb = m >> 10, s = m & 1023;
            int kg = kt + c * 4;
            int hk = kg >> 6, d = kg & 63;
            float4 v = *reinterpret_cast<const float4*>(
                &g_ctx[(((size_t)(bb * NH + hk) * SEQ + s) * HD) + d]);
            __nv_bfloat162 h0, l0, h1, l1;
            split2(v.x, v.y, h0, l0);
            split2(v.z, v.w, h1, l1);
            int o = row * 40 + c * 4;
            *reinterpret_cast<__nv_bfloat162*>(&sAh[o]) = h0;
            *reinterpret_cast<__nv_bfloat162*>(&sAh[o + 2]) = h1;
            *reinterpret_cast<__nv_bfloat162*>(&sAl[o]) = l0;
            *reinterpret_cast<__nv_bfloat162*>(&sAl[o + 2]) = l1;
        }
        stage_rows(sBh, sBl, BT, DMODEL, nb, kt, tid);
        __syncthreads();
        hmma_chunk(sAh, sAl, sBh, sBl, wrow, wcol, g, tig, acc);
        __syncthreads();
    }

#pragma unroll
    for (int mi = 0; mi < 2; ++mi)
#pragma unroll
        for (int ni = 0; ni < 8; ++ni) {
            int col = nb + wcol + ni * 8 + 2 * tig;
            float b0 = bias[col], b1 = bias[col + 1];
#pragma unroll
            for (int half = 0; half < 2; ++half) {
                int row = mb + wrow + mi * 16 + g + half * 8;
                float2 o = make_float2(acc[mi][ni][half * 2 + 0] + b0,
                                       acc[mi][ni][half * 2 + 1] + b1);
                *reinterpret_cast<float2*>(&out[(size_t)row * DMODEL + col]) = o;
            }
        }
}

// ---------------------------------------------------------------------------
// Flash attention via HMMA (byte-identical to passing R9/R11 kernel)
// ---------------------------------------------------------------------------
#define ATTN_SMEM 126976

__global__ __launch_bounds__(256) void attn_hmma()
{
    extern __shared__ char sm[];
    bf16* sQh = (bf16*)(sm + 0);
    bf16* sQl = (bf16*)(sm + 18432);
    bf16* sKVh = (bf16*)(sm + 36864);
    bf16* sKVl = (bf16*)(sm + 46080);
    float* sPt = (float*)(sm + 55296);
    uint32_t* sPh = (uint32_t*)(sm + 89088);
    uint32_t* sPl = (uint32_t*)(sm + 107520);
    float* sAlpha = (float*)(sm + 125952);
    float* sLinv = (float*)(sm + 126464);

    const int tid = threadIdx.x;
    const int wid = tid >> 5, lane = tid & 31;
    const int qb = blockIdx.x * 128;
    const int h = blockIdx.y, b = blockIdx.z;
    const size_t base = ((size_t)(b * NH + h)) * SEQ * HD;
    const float* Qg = g_q + base;
    const float* Kg = g_k + base;
    const float* Vg = g_v + base;

    const int wrow = (wid & 3) * 32;
    const int wcol = (wid >> 2) * 32;
    const int g = lane >> 2, tig = lane & 3;

#pragma unroll
    for (int it = 0; it < 8; ++it) {
        int id = it * 256 + tid;
        int row = id >> 4, c = id & 15;
        float4 v = *reinterpret_cast<const float4*>(
            &Qg[(size_t)(qb + row) * HD + c * 4]);
        __nv_bfloat162 h0, l0, h1, l1;
        split2(v.x, v.y, h0, l0);
        split2(v.z, v.w, h1, l1);
        *reinterpret_cast<__nv_bfloat162*>(&sQh[row * 72 + c * 4]) = h0;
        *reinterpret_cast<__nv_bfloat162*>(&sQh[row * 72 + c * 4 + 2]) = h1;
        *reinterpret_cast<__nv_bfloat162*>(&sQl[row * 72 + c * 4]) = l0;
        *reinterpret_cast<__nv_bfloat162*>(&sQl[row * 72 + c * 4 + 2]) = l1;
    }

    float oacc[2][4][4];
#pragma unroll
    for (int mi = 0; mi < 2; ++mi)
#pragma unroll
        for (int ni = 0; ni < 4; ++ni)
#pragma unroll
            for (int r = 0; r < 4; ++r) oacc[mi][ni][r] = 0.f;
    float m_run = -1e30f, l_run = 0.f;

    for (int kt = 0; kt < SEQ; kt += 64) {
#pragma unroll
        for (int it = 0; it < 4; ++it) {
            int id = it * 256 + tid;
            int j = id >> 4, c = id & 15;
            float4 v = *reinterpret_cast<const float4*>(
                &Kg[(size_t)(kt + j) * HD + c * 4]);
            __nv_bfloat162 h0, l0, h1, l1;
            split2(v.x, v.y, h0, l0);
            split2(v.z, v.w, h1, l1);
            *reinterpret_cast<__nv_bfloat162*>(&sKVh[j * 72 + c * 4]) = h0;
            *reinterpret_cast<__nv_bfloat162*>(&sKVh[j * 72 + c * 4 + 2]) = h1;
            *reinterpret_cast<__nv_bfloat162*>(&sKVl[j * 72 + c * 4]) = l0;
            *reinterpret_cast<__nv_bfloat162*>(&sKVl[j * 72 + c * 4 + 2]) = l1;
        }
        __syncthreads();

        float sacc[2][4][4];
#pragma unroll
        for (int mi = 0; mi < 2; ++mi)
#pragma unroll
            for (int ni = 0; ni < 4; ++ni)
#pragma unroll
                for (int r = 0; r < 4; ++r) sacc[mi][ni][r] = 0.f;

#pragma unroll
        for (int ks = 0; ks < 4; ++ks) {
            const int ko = ks * 16;
            uint32_t ah[2][4], al[2][4];
#pragma unroll
            for (int mi = 0; mi < 2; ++mi) {
                const bf16* p = sQh + (wrow + mi * 16 + g) * 72 + ko + 2 * tig;
                ah[mi][0] = *reinterpret_cast<const uint32_t*>(p);
                ah[mi][1] = *reinterpret_cast<const uint32_t*>(p + 8 * 72);
                ah[mi][2] = *reinterpret_cast<const uint32_t*>(p + 8);
                ah[mi][3] = *reinterpret_cast<const uint32_t*>(p + 8 * 72 + 8);
                const bf16* q = sQl + (wrow + mi * 16 + g) * 72 + ko + 2 * tig;
                al[mi][0] = *reinterpret_cast<const uint32_t*>(q);
                al[mi][1] = *reinterpret_cast<const uint32_t*>(q + 8 * 72);
                al[mi][2] = *reinterpret_cast<const uint32_t*>(q + 8);
                al[mi][3] = *reinterpret_cast<const uint32_t*>(q + 8 * 72 + 8);
            }
            uint32_t bhf[4][2], blf[4][2];
#pragma unroll
            for (int ni = 0; ni < 4; ++ni) {
                const bf16* p = sKVh + (wcol + ni * 8 + g) * 72 + ko + 2 * tig;
                bhf[ni][0] = *reinterpret_cast<const uint32_t*>(p);
                bhf[ni][1] = *reinterpret_cast<const uint32_t*>(p + 8);
                const bf16* q = sKVl + (wcol + ni * 8 + g) * 72 + ko + 2 * tig;
                blf[ni][0] = *reinterpret_cast<const uint32_t*>(q);
                blf[ni][1] = *reinterpret_cast<const uint32_t*>(q + 8);
            }
#pragma unroll
            for (int mi = 0; mi < 2; ++mi)
#pragma unroll
                for (int ni = 0; ni < 4; ++ni) {
                    mma16816(sacc[mi][ni], ah[mi], bhf[ni]);
                    mma16816(sacc[mi][ni], ah[mi], blf[ni]);
                    mma16816(sacc[mi][ni], al[mi], bhf[ni]);
                }
        }

#pragma unroll
        for (int mi = 0; mi < 2; ++mi)
#pragma unroll
            for (int ni = 0; ni < 4; ++ni) {
                int col = wcol + ni * 8 + 2 * tig;
                int row = wrow + mi * 16 + g;
                sPt[col * 132 + row] = sacc[mi][ni][0];
                sPt[(col + 1) * 132 + row] = sacc[mi][ni][1];
                sPt[col * 132 + row + 8] = sacc[mi][ni][2];
                sPt[(col + 1) * 132 + row + 8] = sacc[mi][ni][3];
            }
        __syncthreads();

        if (tid < 128) {
            float tmax = -1e30f;
#pragma unroll 16
            for (int j = 0; j < 64; ++j)
                tmax = fmaxf(tmax, sPt[j * 132 + tid]);
            float m_new = fmaxf(m_run, tmax * ATTN_SCALE);
            float a = __expf(m_run - m_new);
            float sum = 0.f;
#pragma unroll 8
            for (int j2 = 0; j2 < 32; ++j2) {
                float p0 = __expf(fmaf(sPt[(2 * j2) * 132 + tid], ATTN_SCALE, -m_new));
                float p1 = __expf(fmaf(sPt[(2 * j2 + 1) * 132 + tid], ATTN_SCALE, -m_new));
                sum += p0 + p1;
                __nv_bfloat162 hh, ll;
                split2(p0, p1, hh, ll);
                sPh[tid * 36 + j2] = *reinterpret_cast<uint32_t*>(&hh);
                sPl[tid * 36 + j2] = *reinterpret_cast<uint32_t*>(&ll);
            }
            l_run = fmaf(l_run, a, sum);
            m_run = m_new;
            sAlpha[tid] = a;
        } else {
            int t2 = tid - 128;
#pragma unroll
            for (int it = 0; it < 8; ++it) {
                int id = it * 128 + t2;
                int j = id >> 4, c = id & 15;
                float4 v = *reinterpret_cast<const float4*>(
                    &Vg[(size_t)(kt + j) * HD + c * 4]);
                int d = c * 4;
                bf16 h0 = __float2bfloat16(v.x), h1 = __float2bfloat16(v.y);
                bf16 h2 = __float2bfloat16(v.z), h3 = __float2bfloat16(v.w);
                sKVh[(d + 0) * 72 + j] = h0;
                sKVh[(d + 1) * 72 + j] = h1;
                sKVh[(d + 2) * 72 + j] = h2;
                sKVh[(d + 3) * 72 + j] = h3;
                sKVl[(d + 0) * 72 + j] = __float2bfloat16(v.x - __bfloat162float(h0));
                sKVl[(d + 1) * 72 + j] = __float2bfloat16(v.y - __bfloat162float(h1));
                sKVl[(d + 2) * 72 + j] = __float2bfloat16(v.z - __bfloat162float(h2));
                sKVl[(d + 3) * 72 + j] = __float2bfloat16(v.w - __bfloat162float(h3));
            }
        }
        __syncthreads();

        {
            float a0 = sAlpha[wrow + g];
            float a1 = sAlpha[wrow + g + 8];
            float a2 = sAlpha[wrow + g + 16];
            float a3 = sAlpha[wrow + g + 24];
#pragma unroll
            for (int ni = 0; ni < 4; ++ni) {
                oacc[0][ni][0] *= a0; oacc[0][ni][1] *= a0;
                oacc[0][ni][2] *= a1; oacc[0][ni][3] *= a1;
                oacc[1][ni][0] *= a2; oacc[1][ni][1] *= a2;
                oacc[1][ni][2] *= a3; oacc[1][ni][3] *= a3;
            }
        }

#pragma unroll
        for (int ks = 0; ks < 4; ++ks) {
            uint32_t pah[2][4], pal[2][4];
#pragma unroll
            for (int mi = 0; mi < 2; ++mi) {
                int bidx = (wrow + mi * 16 + g) * 36 + ks * 8 + tig;
                pah[mi][0] = sPh[bidx];
                pah[mi][1] = sPh[bidx + 8 * 36];
                pah[mi][2] = sPh[bidx + 4];
                pah[mi][3] = sPh[bidx + 8 * 36 + 4];
                pal[mi][0] = sPl[bidx];
                pal[mi][1] = sPl[bidx + 8 * 36];
                pal[mi][2] = sPl[bidx + 4];
                pal[mi][3] = sPl[bidx + 8 * 36 + 4];
            }
            uint32_t vbh[4][2], vbl[4][2];
#pragma unroll
            for (int ni = 0; ni < 4; ++ni) {
                const bf16* p = sKVh + (wcol + ni * 8 + g) * 72 + ks * 16 + 2 * tig;
                vbh[ni][0] = *reinterpret_cast<const uint32_t*>(p);
                vbh[ni][1] = *reinterpret_cast<const uint32_t*>(p + 8);
                const bf16* q = sKVl + (wcol + ni * 8 + g) * 72 + ks * 16 + 2 * tig;
                vbl[ni][0] = *reinterpret_cast<const uint32_t*>(q);
                vbl[ni][1] = *reinterpret_cast<const uint32_t*>(q + 8);
            }
#pragma unroll
            for (int mi = 0; mi < 2; ++mi)
#pragma unroll
                for (int ni = 0; ni < 4; ++ni) {
                    mma16816(oacc[mi][ni], pah[mi], vbh[ni]);
                    mma16816(oacc[mi][ni], pah[mi], vbl[ni]);
                    mma16816(oacc[mi][ni], pal[mi], vbh[ni]);
                }
        }
        __syncthreads();
    }

    if (tid < 128) sLinv[tid] = 1.f / l_run;
    __syncthreads();

    float* Og = g_ctx + base;
#pragma unroll
    for (int mi = 0; mi < 2; ++mi) {
        int r0 = wrow + mi * 16 + g;
        float inv0 = sLinv[r0], inv1 = sLinv[r0 + 8];
#pragma unroll
        for (int ni = 0; ni < 4; ++ni) {
            int col = wcol + ni * 8 + 2 * tig;
            *reinterpret_cast<float2*>(&Og[(size_t)(qb + r0) * HD + col]) =
                make_float2(oacc[mi][ni][0] * inv0, oacc[mi][ni][1] * inv0);
            *reinterpret_cast<float2*>(&Og[(size_t)(qb + r0 + 8) * HD + col]) =
                make_float2(oacc[mi][ni][2] * inv1, oacc[mi][ni][3] * inv1);
        }
    }
}

// ---------------------------------------------------------------------------
extern "C" void kernel_launch(void* const* d_in, const int* in_sizes, int n_in,
                              void* d_out, int out_size)
{
    const float* hidden = (const float*)d_in[0];
    const float* w_qkv  = (const float*)d_in[1];
    const float* b_qkv  = (const float*)d_in[2];
    const float* w_proj = (const float*)d_in[3];
    const float* b_proj = (const float*)d_in[4];
    float* out = (float*)d_out;

    cudaFuncSetAttribute(attn_hmma,
                         cudaFuncAttributeMaxDynamicSharedMemorySize, ATTN_SMEM);

    transpose_wqkv<<<dim3(NQKV / 32, DMODEL / 32), dim3(32, 8)>>>(w_qkv);
    transpose_wproj<<<dim3(DMODEL / 32, DMODEL / 32), dim3(32, 8)>>>(w_proj);

    qkv_gemm_hmma<<<dim3(NQKV / 128, MTOT / 128), 256>>>(hidden, b_qkv);
    attn_hmma<<<dim3(SEQ / 128, NH, BATCH), 256, ATTN_SMEM>>>();
    proj_gemm_hmma<<<dim3(DMODEL / 128, MTOT / 128), 256>>>(b_proj, out);
}

// round 15
// speedup vs baseline: 4.9560x; 1.2386x over previous
#include <cuda_runtime.h>
#include <cuda_bf16.h>
#include <math.h>
#include <stdint.h>

#define BATCH 8
#define SEQ 1024
#define DMODEL 768
#define NH 12
#define HD 64
#define ATTN_SCALE 0.125f
#define MTOT (BATCH * SEQ)         /* 8192 */
#define NQKV (3 * DMODEL)          /* 2304 */

typedef __nv_bfloat16 bf16;

// ---------------------------------------------------------------------------
// Scratch — fp32 only; referenced ONLY from device code (GB300 ATS pitfall:
// host-side __device__ symbol addresses silently route via NVLink-C2C).
// ---------------------------------------------------------------------------
__device__ float g_q[BATCH * NH * SEQ * HD];
__device__ float g_k[BATCH * NH * SEQ * HD];
__device__ float g_v[BATCH * NH * SEQ * HD];
__device__ float g_ctx[BATCH * NH * SEQ * HD];
__device__ float g_wqkvT[NQKV * DMODEL];      // [N][K] fp32
__device__ float g_wprojT[DMODEL * DMODEL];   // [N][K] fp32

// ---------------------------------------------------------------------------
// HMMA helper (m16n8k16, bf16 in / fp32 accumulate)
// ---------------------------------------------------------------------------
__device__ __forceinline__ void mma16816(float* c, const uint32_t* a,
                                         const uint32_t* b) {
    asm volatile(
        "mma.sync.aligned.m16n8k16.row.col.f32.bf16.bf16.f32 "
        "{%0,%1,%2,%3}, {%4,%5,%6,%7}, {%8,%9}, {%0,%1,%2,%3};"
        : "+f"(c[0]), "+f"(c[1]), "+f"(c[2]), "+f"(c[3])
        : "r"(a[0]), "r"(a[1]), "r"(a[2]), "r"(a[3]), "r"(b[0]), "r"(b[1]));
}

__device__ __forceinline__ void split2(float v0, float v1,
                                       __nv_bfloat162& h, __nv_bfloat162& l) {
    bf16 h0 = __float2bfloat16(v0), h1 = __float2bfloat16(v1);
    h = __halves2bfloat162(h0, h1);
    l = __halves2bfloat162(__float2bfloat16(v0 - __bfloat162float(h0)),
                           __float2bfloat16(v1 - __bfloat162float(h1)));
}

// ---------------------------------------------------------------------------
// fp32 transposes into device globals (device-side reference only)
// ---------------------------------------------------------------------------
__device__ __forceinline__ void transpose_body(
    const float* __restrict__ W, float* __restrict__ WT, int N, int K)
{
    __shared__ float t[32][33];
    int n0 = blockIdx.x * 32, k0 = blockIdx.y * 32;
    int tx = threadIdx.x, ty = threadIdx.y;
#pragma unroll
    for (int i = 0; i < 4; ++i)
        t[ty + i * 8][tx] = W[(size_t)(k0 + ty + i * 8) * N + n0 + tx];
    __syncthreads();
#pragma unroll
    for (int i = 0; i < 4; ++i) {
        int n = ty + i * 8;
        WT[(size_t)(n0 + n) * K + k0 + tx] = t[tx][n];
    }
}

__global__ void transpose_wqkv(const float* __restrict__ W)
{
    transpose_body(W, g_wqkvT, NQKV, DMODEL);
}

__global__ void transpose_wproj(const float* __restrict__ W)
{
    transpose_body(W, g_wprojT, DMODEL, DMODEL);
}

// ---------------------------------------------------------------------------
// Shared HMMA compute for one staged 32-k chunk (bf16 hi/lo smem, stride 40).
// ---------------------------------------------------------------------------
__device__ __forceinline__ void hmma_chunk(
    const bf16* sAh, const bf16* sAl, const bf16* sBh, const bf16* sBl,
    int wrow, int wcol, int g, int tig, float acc[2][8][4])
{
#pragma unroll
    for (int ks = 0; ks < 2; ++ks) {
        const int ko = ks * 16;
        uint32_t ah[2][4], al[2][4];
#pragma unroll
        for (int mi = 0; mi < 2; ++mi) {
            const bf16* p = sAh + (wrow + mi * 16 + g) * 40 + ko + 2 * tig;
            ah[mi][0] = *reinterpret_cast<const uint32_t*>(p);
            ah[mi][1] = *reinterpret_cast<const uint32_t*>(p + 8 * 40);
            ah[mi][2] = *reinterpret_cast<const uint32_t*>(p + 8);
            ah[mi][3] = *reinterpret_cast<const uint32_t*>(p + 8 * 40 + 8);
            const bf16* q = sAl + (wrow + mi * 16 + g) * 40 + ko + 2 * tig;
            al[mi][0] = *reinterpret_cast<const uint32_t*>(q);
            al[mi][1] = *reinterpret_cast<const uint32_t*>(q + 8 * 40);
            al[mi][2] = *reinterpret_cast<const uint32_t*>(q + 8);
            al[mi][3] = *reinterpret_cast<const uint32_t*>(q + 8 * 40 + 8);
        }
        uint32_t bhf[8][2], blf[8][2];
#pragma unroll
        for (int ni = 0; ni < 8; ++ni) {
            const bf16* p = sBh + (wcol + ni * 8 + g) * 40 + ko + 2 * tig;
            bhf[ni][0] = *reinterpret_cast<const uint32_t*>(p);
            bhf[ni][1] = *reinterpret_cast<const uint32_t*>(p + 8);
            const bf16* q = sBl + (wcol + ni * 8 + g) * 40 + ko + 2 * tig;
            blf[ni][0] = *reinterpret_cast<const uint32_t*>(q);
            blf[ni][1] = *reinterpret_cast<const uint32_t*>(q + 8);
        }
#pragma unroll
        for (int mi = 0; mi < 2; ++mi)
#pragma unroll
            for (int ni = 0; ni < 8; ++ni) {
                mma16816(acc[mi][ni], ah[mi], bhf[ni]);
                mma16816(acc[mi][ni], ah[mi], blf[ni]);
                mma16816(acc[mi][ni], al[mi], bhf[ni]);
            }
    }
}

// Stage one [128 rows][32 k] fp32 tile into split bf16 smem (stride 40).
__device__ __forceinline__ void stage_rows(
    bf16* sh, bf16* sl, const float* __restrict__ G, int rowstride,
    int rowbase, int kt, int tid)
{
#pragma unroll
    for (int it = 0; it < 4; ++it) {
        int id = it * 256 + tid;
        int row = id >> 3, c = id & 7;
        float4 v = *reinterpret_cast<const float4*>(
            &G[(size_t)(rowbase + row) * rowstride + kt + c * 4]);
        __nv_bfloat162 h0, l0, h1, l1;
        split2(v.x, v.y, h0, l0);
        split2(v.z, v.w, h1, l1);
        int o = row * 40 + c * 4;
        *reinterpret_cast<__nv_bfloat162*>(&sh[o]) = h0;
        *reinterpret_cast<__nv_bfloat162*>(&sh[o + 2]) = h1;
        *reinterpret_cast<__nv_bfloat162*>(&sl[o]) = l0;
        *reinterpret_cast<__nv_bfloat162*>(&sl[o + 2]) = l1;
    }
}

// ---------------------------------------------------------------------------
// QKV GEMM (byte-identical to passing R14)
// ---------------------------------------------------------------------------
__global__ __launch_bounds__(256) void qkv_gemm_hmma(
    const float* __restrict__ A, const float* __restrict__ bias)
{
    __shared__ bf16 smem[512 * 40];
    bf16* sAh = smem;
    bf16* sAl = smem + 128 * 40;
    bf16* sBh = smem + 256 * 40;
    bf16* sBl = smem + 384 * 40;

    const float* BT = g_wqkvT;

    const int tid = threadIdx.x;
    const int wid = tid >> 5, lane = tid & 31;
    const int nb = blockIdx.x * 128, mb = blockIdx.y * 128;
    const int wrow = (wid & 3) * 32;
    const int wcol = (wid >> 2) * 64;
    const int g = lane >> 2, tig = lane & 3;

    float acc[2][8][4];
#pragma unroll
    for (int mi = 0; mi < 2; ++mi)
#pragma unroll
        for (int ni = 0; ni < 8; ++ni)
#pragma unroll
            for (int r = 0; r < 4; ++r) acc[mi][ni][r] = 0.f;

#pragma unroll 1
    for (int i = 0; i < 24; ++i) {
        stage_rows(sAh, sAl, A, DMODEL, mb, i * 32, tid);
        stage_rows(sBh, sBl, BT, DMODEL, nb, i * 32, tid);
        __syncthreads();
        hmma_chunk(sAh, sAl, sBh, sBl, wrow, wcol, g, tig, acc);
        __syncthreads();
    }

#pragma unroll
    for (int mi = 0; mi < 2; ++mi)
#pragma unroll
        for (int ni = 0; ni < 8; ++ni) {
            int col = nb + wcol + ni * 8 + 2 * tig;
            int which = col / DMODEL;
            int rem = col - which * DMODEL;
            int h = rem >> 6, d = rem & 63;
            float* dst = (which == 0) ? g_q : ((which == 1) ? g_k : g_v);
            float b0 = bias[col], b1 = bias[col + 1];
#pragma unroll
            for (int half = 0; half < 2; ++half) {
                int m = mb + wrow + mi * 16 + g + half * 8;
                int bb = m >> 10, s = m & 1023;
                float2 o = make_float2(acc[mi][ni][half * 2 + 0] + b0,
                                       acc[mi][ni][half * 2 + 1] + b1);
                *reinterpret_cast<float2*>(
                    &dst[(((size_t)(bb * NH + h) * SEQ + s) * HD) + d]) = o;
            }
        }
}

// ---------------------------------------------------------------------------
// Proj GEMM (byte-identical to passing R14)
// ---------------------------------------------------------------------------
__global__ __launch_bounds__(256) void proj_gemm_hmma(
    const float* __restrict__ bias, float* __restrict__ out)
{
    __shared__ bf16 smem[512 * 40];
    bf16* sAh = smem;
    bf16* sAl = smem + 128 * 40;
    bf16* sBh = smem + 256 * 40;
    bf16* sBl = smem + 384 * 40;

    const float* BT = g_wprojT;

    const int tid = threadIdx.x;
    const int wid = tid >> 5, lane = tid & 31;
    const int nb = blockIdx.x * 128, mb = blockIdx.y * 128;
    const int wrow = (wid & 3) * 32;
    const int wcol = (wid >> 2) * 64;
    const int g = lane >> 2, tig = lane & 3;

    float acc[2][8][4];
#pragma unroll
    for (int mi = 0; mi < 2; ++mi)
#pragma unroll
        for (int ni = 0; ni < 8; ++ni)
#pragma unroll
            for (int r = 0; r < 4; ++r) acc[mi][ni][r] = 0.f;

#pragma unroll 1
    for (int i = 0; i < 24; ++i) {
        int kt = i * 32;
#pragma unroll
        for (int it = 0; it < 4; ++it) {
            int id = it * 256 + tid;
            int row = id >> 3, c = id & 7;
            int m = mb + row;
            int bb = m >> 10, s = m & 1023;
            int kg = kt + c * 4;
            int hk = kg >> 6, d = kg & 63;
            float4 v = *reinterpret_cast<const float4*>(
                &g_ctx[(((size_t)(bb * NH + hk) * SEQ + s) * HD) + d]);
            __nv_bfloat162 h0, l0, h1, l1;
            split2(v.x, v.y, h0, l0);
            split2(v.z, v.w, h1, l1);
            int o = row * 40 + c * 4;
            *reinterpret_cast<__nv_bfloat162*>(&sAh[o]) = h0;
            *reinterpret_cast<__nv_bfloat162*>(&sAh[o + 2]) = h1;
            *reinterpret_cast<__nv_bfloat162*>(&sAl[o]) = l0;
            *reinterpret_cast<__nv_bfloat162*>(&sAl[o + 2]) = l1;
        }
        stage_rows(sBh, sBl, BT, DMODEL, nb, kt, tid);
        __syncthreads();
        hmma_chunk(sAh, sAl, sBh, sBl, wrow, wcol, g, tig, acc);
        __syncthreads();
    }

#pragma unroll
    for (int mi = 0; mi < 2; ++mi)
#pragma unroll
        for (int ni = 0; ni < 8; ++ni) {
            int col = nb + wcol + ni * 8 + 2 * tig;
            float b0 = bias[col], b1 = bias[col + 1];
#pragma unroll
            for (int half = 0; half < 2; ++half) {
                int row = mb + wrow + mi * 16 + g + half * 8;
                float2 o = make_float2(acc[mi][ni][half * 2 + 0] + b0,
                                       acc[mi][ni][half * 2 + 1] + b1);
                *reinterpret_cast<float2*>(&out[(size_t)row * DMODEL + col]) = o;
            }
        }
}

// ---------------------------------------------------------------------------
// Flash attention, register-resident softmax (FA2-style).
// smem (bytes): sQh 0, sQl 18432, sKVh 36864, sKVl 46080,
//               sPh 55296 [128*36 u32], sPl 73728, sMax 92160, sSum 93184.
// Total 94208 -> 2 CTAs/SM if regs <= 128.
// ---------------------------------------------------------------------------
#define ATTN_SMEM 94208

__global__ __launch_bounds__(256) void attn_hmma()
{
    extern __shared__ char sm[];
    bf16* sQh = (bf16*)(sm + 0);
    bf16* sQl = (bf16*)(sm + 18432);
    bf16* sKVh = (bf16*)(sm + 36864);
    bf16* sKVl = (bf16*)(sm + 46080);
    uint32_t* sPh = (uint32_t*)(sm + 55296);
    uint32_t* sPl = (uint32_t*)(sm + 73728);
    float* sMax = (float*)(sm + 92160);   // [128][2]
    float* sSum = (float*)(sm + 93184);   // [128][2]

    const int tid = threadIdx.x;
    const int wid = tid >> 5, lane = tid & 31;
    const int qb = blockIdx.x * 128;
    const int h = blockIdx.y, b = blockIdx.z;
    const size_t base = ((size_t)(b * NH + h)) * SEQ * HD;
    const float* Qg = g_q + base;
    const float* Kg = g_k + base;
    const float* Vg = g_v + base;

    const int wrow = (wid & 3) * 32;
    const int kvh = wid >> 2;            // kv half (0/1); also d half for PV
    const int wcol = kvh * 32;
    const int g = lane >> 2, tig = lane & 3;

    // ---- Stage Q once (hi/lo, stride 72) ----
#pragma unroll
    for (int it = 0; it < 8; ++it) {
        int id = it * 256 + tid;
        int row = id >> 4, c = id & 15;
        float4 v = *reinterpret_cast<const float4*>(
            &Qg[(size_t)(qb + row) * HD + c * 4]);
        __nv_bfloat162 h0, l0, h1, l1;
        split2(v.x, v.y, h0, l0);
        split2(v.z, v.w, h1, l1);
        *reinterpret_cast<__nv_bfloat162*>(&sQh[row * 72 + c * 4]) = h0;
        *reinterpret_cast<__nv_bfloat162*>(&sQh[row * 72 + c * 4 + 2]) = h1;
        *reinterpret_cast<__nv_bfloat162*>(&sQl[row * 72 + c * 4]) = l0;
        *reinterpret_cast<__nv_bfloat162*>(&sQl[row * 72 + c * 4 + 2]) = l1;
    }

    float oacc[2][4][4];
#pragma unroll
    for (int mi = 0; mi < 2; ++mi)
#pragma unroll
        for (int ni = 0; ni < 4; ++ni)
#pragma unroll
            for (int r = 0; r < 4; ++r) oacc[mi][ni][r] = 0.f;
    float m_run[2][2] = {{-1e30f, -1e30f}, {-1e30f, -1e30f}};
    float l_run[2][2] = {{0.f, 0.f}, {0.f, 0.f}};

    for (int kt = 0; kt < SEQ; kt += 64) {
        // ---- Stage K tile [64 kv][64 d] natural (hi/lo) ----
#pragma unroll
        for (int it = 0; it < 4; ++it) {
            int id = it * 256 + tid;
            int j = id >> 4, c = id & 15;
            float4 v = *reinterpret_cast<const float4*>(
                &Kg[(size_t)(kt + j) * HD + c * 4]);
            __nv_bfloat162 h0, l0, h1, l1;
            split2(v.x, v.y, h0, l0);
            split2(v.z, v.w, h1, l1);
            *reinterpret_cast<__nv_bfloat162*>(&sKVh[j * 72 + c * 4]) = h0;
            *reinterpret_cast<__nv_bfloat162*>(&sKVh[j * 72 + c * 4 + 2]) = h1;
            *reinterpret_cast<__nv_bfloat162*>(&sKVl[j * 72 + c * 4]) = l0;
            *reinterpret_cast<__nv_bfloat162*>(&sKVl[j * 72 + c * 4 + 2]) = l1;
        }
        __syncthreads();

        // ---- S = Q K^T (warp: 32 rows x its 32-kv half), 3-term HMMA ----
        float sacc[2][4][4];
#pragma unroll
        for (int mi = 0; mi < 2; ++mi)
#pragma unroll
            for (int ni = 0; ni < 4; ++ni)
#pragma unroll
                for (int r = 0; r < 4; ++r) sacc[mi][ni][r] = 0.f;

#pragma unroll
        for (int ks = 0; ks < 4; ++ks) {
            const int ko = ks * 16;
            uint32_t ah[2][4], al[2][4];
#pragma unroll
            for (int mi = 0; mi < 2; ++mi) {
                const bf16* p = sQh + (wrow + mi * 16 + g) * 72 + ko + 2 * tig;
                ah[mi][0] = *reinterpret_cast<const uint32_t*>(p);
                ah[mi][1] = *reinterpret_cast<const uint32_t*>(p + 8 * 72);
                ah[mi][2] = *reinterpret_cast<const uint32_t*>(p + 8);
                ah[mi][3] = *reinterpret_cast<const uint32_t*>(p + 8 * 72 + 8);
                const bf16* q = sQl + (wrow + mi * 16 + g) * 72 + ko + 2 * tig;
                al[mi][0] = *reinterpret_cast<const uint32_t*>(q);
                al[mi][1] = *reinterpret_cast<const uint32_t*>(q + 8 * 72);
                al[mi][2] = *reinterpret_cast<const uint32_t*>(q + 8);
                al[mi][3] = *reinterpret_cast<const uint32_t*>(q + 8 * 72 + 8);
            }
            uint32_t bhf[4][2], blf[4][2];
#pragma unroll
            for (int ni = 0; ni < 4; ++ni) {
                const bf16* p = sKVh + (wcol + ni * 8 + g) * 72 + ko + 2 * tig;
                bhf[ni][0] = *reinterpret_cast<const uint32_t*>(p);
                bhf[ni][1] = *reinterpret_cast<const uint32_t*>(p + 8);
                const bf16* q = sKVl + (wcol + ni * 8 + g) * 72 + ko + 2 * tig;
                blf[ni][0] = *reinterpret_cast<const uint32_t*>(q);
                blf[ni][1] = *reinterpret_cast<const uint32_t*>(q + 8);
            }
#pragma unroll
            for (int mi = 0; mi < 2; ++mi)
#pragma unroll
                for (int ni = 0; ni < 4; ++ni) {
                    mma16816(sacc[mi][ni], ah[mi], bhf[ni]);
                    mma16816(sacc[mi][ni], ah[mi], blf[ni]);
                    mma16816(sacc[mi][ni], al[mi], bhf[ni]);
                }
        }

        // ---- Partial row max over this warp's 32 kv (quad shuffle) ----
#pragma unroll
        for (int mi = 0; mi < 2; ++mi)
#pragma unroll
            for (int half = 0; half < 2; ++half) {
                float pm = -1e30f;
#pragma unroll
                for (int ni = 0; ni < 4; ++ni) {
                    pm = fmaxf(pm, sacc[mi][ni][half * 2 + 0]);
                    pm = fmaxf(pm, sacc[mi][ni][half * 2 + 1]);
                }
                pm = fmaxf(pm, __shfl_xor_sync(0xffffffffu, pm, 1));
                pm = fmaxf(pm, __shfl_xor_sync(0xffffffffu, pm, 2));
                int row = wrow + mi * 16 + half * 8 + g;
                sMax[row * 2 + kvh] = pm;    // quad lanes write same value
            }
        __syncthreads();

        // ---- Combine max, exp (regs), pack P, stage V, partial sums ----
        float alpha[2][2];
#pragma unroll
        for (int mi = 0; mi < 2; ++mi)
#pragma unroll
            for (int half = 0; half < 2; ++half) {
                int row = wrow + mi * 16 + half * 8 + g;
                float mt = fmaxf(sMax[row * 2], sMax[row * 2 + 1]) * ATTN_SCALE;
                float mnew = fmaxf(m_run[mi][half], mt);
                alpha[mi][half] = __expf(m_run[mi][half] - mnew);
                m_run[mi][half] = mnew;
            }
#pragma unroll
        for (int mi = 0; mi < 2; ++mi)
#pragma unroll
            for (int ni = 0; ni < 4; ++ni)
#pragma unroll
                for (int r = 0; r < 4; ++r)
                    sacc[mi][ni][r] = __expf(
                        fmaf(sacc[mi][ni][r], ATTN_SCALE, -m_run[mi][r >> 1]));

#pragma unroll
        for (int mi = 0; mi < 2; ++mi)
#pragma unroll
            for (int half = 0; half < 2; ++half) {
                float ps = 0.f;
#pragma unroll
                for (int ni = 0; ni < 4; ++ni)
                    ps += sacc[mi][ni][half * 2 + 0] + sacc[mi][ni][half * 2 + 1];
                ps += __shfl_xor_sync(0xffffffffu, ps, 1);
                ps += __shfl_xor_sync(0xffffffffu, ps, 2);
                int row = wrow + mi * 16 + half * 8 + g;
                sSum[row * 2 + kvh] = ps;
            }

        // Pack P into fragment-layout smem (same layout PV already reads)
#pragma unroll
        for (int mi = 0; mi < 2; ++mi)
#pragma unroll
            for (int ni = 0; ni < 4; ++ni) {
                int row0 = wrow + mi * 16 + g;
                int idx = kvh * 16 + ni * 4 + tig;
                __nv_bfloat162 hh, ll;
                split2(sacc[mi][ni][0], sacc[mi][ni][1], hh, ll);
                sPh[row0 * 36 + idx] = *reinterpret_cast<uint32_t*>(&hh);
                sPl[row0 * 36 + idx] = *reinterpret_cast<uint32_t*>(&ll);
                split2(sacc[mi][ni][2], sacc[mi][ni][3], hh, ll);
                sPh[(row0 + 8) * 36 + idx] = *reinterpret_cast<uint32_t*>(&hh);
                sPl[(row0 + 8) * 36 + idx] = *reinterpret_cast<uint32_t*>(&ll);
            }

        // Stage V^T [d][kv] (hi/lo) — K data dead
#pragma unroll
        for (int it = 0; it < 4; ++it) {
            int id = it * 256 + tid;
            int j = id >> 4, c = id & 15;
            float4 v = *reinterpret_cast<const float4*>(
                &Vg[(size_t)(kt + j) * HD + c * 4]);
            int d = c * 4;
            bf16 h0 = __float2bfloat16(v.x), h1 = __float2bfloat16(v.y);
            bf16 h2 = __float2bfloat16(v.z), h3 = __float2bfloat16(v.w);
            sKVh[(d + 0) * 72 + j] = h0;
            sKVh[(d + 1) * 72 + j] = h1;
            sKVh[(d + 2) * 72 + j] = h2;
            sKVh[(d + 3) * 72 + j] = h3;
            sKVl[(d + 0) * 72 + j] = __float2bfloat16(v.x - __bfloat162float(h0));
            sKVl[(d + 1) * 72 + j] = __float2bfloat16(v.y - __bfloat162float(h1));
            sKVl[(d + 2) * 72 + j] = __float2bfloat16(v.z - __bfloat162float(h2));
            sKVl[(d + 3) * 72 + j] = __float2bfloat16(v.w - __bfloat162float(h3));
        }
        __syncthreads();

        // ---- l_run update + O rescale ----
#pragma unroll
        for (int mi = 0; mi < 2; ++mi)
#pragma unroll
            for (int half = 0; half < 2; ++half) {
                int row = wrow + mi * 16 + half * 8 + g;
                float st = sSum[row * 2] + sSum[row * 2 + 1];
                l_run[mi][half] = fmaf(l_run[mi][half], alpha[mi][half], st);
            }
#pragma unroll
        for (int mi = 0; mi < 2; ++mi)
#pragma unroll
            for (int ni = 0; ni < 4; ++ni)
#pragma unroll
                for (int r = 0; r < 4; ++r)
                    oacc[mi][ni][r] *= alpha[mi][r >> 1];

        // ---- O += P V (full kv=64, d = warp's 32-col half) ----
#pragma unroll
        for (int ks = 0; ks < 4; ++ks) {
            uint32_t pah[2][4], pal[2][4];
#pragma unroll
            for (int mi = 0; mi < 2; ++mi) {
                int bidx = (wrow + mi * 16 + g) * 36 + ks * 8 + tig;
                pah[mi][0] = sPh[bidx];
                pah[mi][1] = sPh[bidx + 8 * 36];
                pah[mi][2] = sPh[bidx + 4];
                pah[mi][3] = sPh[bidx + 8 * 36 + 4];
                pal[mi][0] = sPl[bidx];
                pal[mi][1] = sPl[bidx + 8 * 36];
                pal[mi][2] = sPl[bidx + 4];
                pal[mi][3] = sPl[bidx + 8 * 36 + 4];
            }
            uint32_t vbh[4][2], vbl[4][2];
#pragma unroll
            for (int ni = 0; ni < 4; ++ni) {
                const bf16* p = sKVh + (wcol + ni * 8 + g) * 72 + ks * 16 + 2 * tig;
                vbh[ni][0] = *reinterpret_cast<const uint32_t*>(p);
                vbh[ni][1] = *reinterpret_cast<const uint32_t*>(p + 8);
                const bf16* q = sKVl + (wcol + ni * 8 + g) * 72 + ks * 16 + 2 * tig;
                vbl[ni][0] = *reinterpret_cast<const uint32_t*>(q);
                vbl[ni][1] = *reinterpret_cast<const uint32_t*>(q + 8);
            }
#pragma unroll
            for (int mi = 0; mi < 2; ++mi)
#pragma unroll
                for (int ni = 0; ni < 4; ++ni) {
                    mma16816(oacc[mi][ni], pah[mi], vbh[ni]);
                    mma16816(oacc[mi][ni], pah[mi], vbl[ni]);
                    mma16816(oacc[mi][ni], pal[mi], vbh[ni]);
                }
        }
        __syncthreads();
    }

    // ---- Epilogue: normalize by l_run (per-thread registers) ----
    float* Og = g_ctx + base;
#pragma unroll
    for (int mi = 0; mi < 2; ++mi) {
        int r0 = wrow + mi * 16 + g;
        float inv0 = 1.f / l_run[mi][0];
        float inv1 = 1.f / l_run[mi][1];
#pragma unroll
        for (int ni = 0; ni < 4; ++ni) {
            int col = wcol + ni * 8 + 2 * tig;
            *reinterpret_cast<float2*>(&Og[(size_t)(qb + r0) * HD + col]) =
                make_float2(oacc[mi][ni][0] * inv0, oacc[mi][ni][1] * inv0);
            *reinterpret_cast<float2*>(&Og[(size_t)(qb + r0 + 8) * HD + col]) =
                make_float2(oacc[mi][ni][2] * inv1, oacc[mi][ni][3] * inv1);
        }
    }
}

// ---------------------------------------------------------------------------
extern "C" void kernel_launch(void* const* d_in, const int* in_sizes, int n_in,
                              void* d_out, int out_size)
{
    const float* hidden = (const float*)d_in[0];
    const float* w_qkv  = (const float*)d_in[1];
    const float* b_qkv  = (const float*)d_in[2];
    const float* w_proj = (const float*)d_in[3];
    const float* b_proj = (const float*)d_in[4];
    float* out = (float*)d_out;

    cudaFuncSetAttribute(attn_hmma,
                         cudaFuncAttributeMaxDynamicSharedMemorySize, ATTN_SMEM);

    transpose_wqkv<<<dim3(NQKV / 32, DMODEL / 32), dim3(32, 8)>>>(w_qkv);
    transpose_wproj<<<dim3(DMODEL / 32, DMODEL / 32), dim3(32, 8)>>>(w_proj);

    qkv_gemm_hmma<<<dim3(NQKV / 128, MTOT / 128), 256>>>(hidden, b_qkv);
    attn_hmma<<<dim3(SEQ / 128, NH, BATCH), 256, ATTN_SMEM>>>();
    proj_gemm_hmma<<<dim3(DMODEL / 128, MTOT / 128), 256>>>(b_proj, out);
}

// round 16
// speedup vs baseline: 5.5370x; 1.1172x over previous
#include <cuda_runtime.h>
#include <cuda_bf16.h>
#include <math.h>
#include <stdint.h>

#define BATCH 8
#define SEQ 1024
#define DMODEL 768
#define NH 12
#define HD 64
#define ATTN_SCALE 0.125f
#define MTOT (BATCH * SEQ)         /* 8192 */
#define NQKV (3 * DMODEL)          /* 2304 */

typedef __nv_bfloat16 bf16;

// ---------------------------------------------------------------------------
// Scratch — referenced ONLY from device code (GB300 ATS pitfall: host-side
// __device__ symbol addresses silently route to host-shadow memory).
// ---------------------------------------------------------------------------
__device__ float g_q[BATCH * NH * SEQ * HD];
__device__ float g_k[BATCH * NH * SEQ * HD];
__device__ float g_v[BATCH * NH * SEQ * HD];

__device__ __align__(16) bf16 g_h_hi[MTOT * DMODEL];
__device__ __align__(16) bf16 g_h_lo[MTOT * DMODEL];
__device__ __align__(16) bf16 g_wqkvT_hi[NQKV * DMODEL];    // [N][K]
__device__ __align__(16) bf16 g_wqkvT_lo[NQKV * DMODEL];
__device__ __align__(16) bf16 g_wprojT_hi[DMODEL * DMODEL]; // [N][K]
__device__ __align__(16) bf16 g_wprojT_lo[DMODEL * DMODEL];
__device__ __align__(16) bf16 g_ctx_hi[MTOT * DMODEL];      // [m][768]
__device__ __align__(16) bf16 g_ctx_lo[MTOT * DMODEL];

// ---------------------------------------------------------------------------
// Helpers
// ---------------------------------------------------------------------------
__device__ __forceinline__ void mma16816(float* c, const uint32_t* a,
                                         const uint32_t* b) {
    asm volatile(
        "mma.sync.aligned.m16n8k16.row.col.f32.bf16.bf16.f32 "
        "{%0,%1,%2,%3}, {%4,%5,%6,%7}, {%8,%9}, {%0,%1,%2,%3};"
        : "+f"(c[0]), "+f"(c[1]), "+f"(c[2]), "+f"(c[3])
        : "r"(a[0]), "r"(a[1]), "r"(a[2]), "r"(a[3]), "r"(b[0]), "r"(b[1]));
}

__device__ __forceinline__ void split2(float v0, float v1,
                                       __nv_bfloat162& h, __nv_bfloat162& l) {
    bf16 h0 = __float2bfloat16(v0), h1 = __float2bfloat16(v1);
    h = __halves2bfloat162(h0, h1);
    l = __halves2bfloat162(__float2bfloat16(v0 - __bfloat162float(h0)),
                           __float2bfloat16(v1 - __bfloat162float(h1)));
}

#define CP_ASYNC16(saddr, gptr) \
    asm volatile("cp.async.cg.shared.global [%0], [%1], 16;" \
                 :: "r"(saddr), "l"(gptr) : "memory")
#define CP_COMMIT() asm volatile("cp.async.commit_group;" ::: "memory")
#define CP_WAIT_1() asm volatile("cp.async.wait_group 1;" ::: "memory")
#define CP_WAIT_0() asm volatile("cp.async.wait_group 0;" ::: "memory")

// ---------------------------------------------------------------------------
// Pre-split converters (device-global outputs referenced in device code)
// ---------------------------------------------------------------------------
__global__ __launch_bounds__(256) void conv_hidden(const float* __restrict__ src)
{
    int i = blockIdx.x * 256 + threadIdx.x;
    float4 v = reinterpret_cast<const float4*>(src)[i];
    __nv_bfloat162 h0, l0, h1, l1;
    split2(v.x, v.y, h0, l0);
    split2(v.z, v.w, h1, l1);
    int o = i * 4;
    *reinterpret_cast<__nv_bfloat162*>(&g_h_hi[o]) = h0;
    *reinterpret_cast<__nv_bfloat162*>(&g_h_hi[o + 2]) = h1;
    *reinterpret_cast<__nv_bfloat162*>(&g_h_lo[o]) = l0;
    *reinterpret_cast<__nv_bfloat162*>(&g_h_lo[o + 2]) = l1;
}

__device__ __forceinline__ void tsplit_body(
    const float* __restrict__ W, bf16* __restrict__ WTh,
    bf16* __restrict__ WTl, int N, int K)
{
    __shared__ float t[32][33];
    int n0 = blockIdx.x * 32, k0 = blockIdx.y * 32;
    int tx = threadIdx.x, ty = threadIdx.y;
#pragma unroll
    for (int i = 0; i < 4; ++i)
        t[ty + i * 8][tx] = W[(size_t)(k0 + ty + i * 8) * N + n0 + tx];
    __syncthreads();
#pragma unroll
    for (int i = 0; i < 4; ++i) {
        int n = ty + i * 8;
        float v = t[tx][n];
        bf16 h = __float2bfloat16(v);
        size_t o = (size_t)(n0 + n) * K + k0 + tx;
        WTh[o] = h;
        WTl[o] = __float2bfloat16(v - __bfloat162float(h));
    }
}

__global__ void transpose_wqkv(const float* __restrict__ W)
{
    tsplit_body(W, g_wqkvT_hi, g_wqkvT_lo, NQKV, DMODEL);
}

__global__ void transpose_wproj(const float* __restrict__ W)
{
    tsplit_body(W, g_wprojT_hi, g_wprojT_lo, DMODEL, DMODEL);
}

// ---------------------------------------------------------------------------
// Shared HMMA compute for one staged 32-k chunk (bf16 hi/lo smem, stride 40).
// ---------------------------------------------------------------------------
__device__ __forceinline__ void hmma_chunk(
    const bf16* sAh, const bf16* sAl, const bf16* sBh, const bf16* sBl,
    int wrow, int wcol, int g, int tig, float acc[2][8][4])
{
#pragma unroll
    for (int ks = 0; ks < 2; ++ks) {
        const int ko = ks * 16;
        uint32_t ah[2][4], al[2][4];
#pragma unroll
        for (int mi = 0; mi < 2; ++mi) {
            const bf16* p = sAh + (wrow + mi * 16 + g) * 40 + ko + 2 * tig;
            ah[mi][0] = *reinterpret_cast<const uint32_t*>(p);
            ah[mi][1] = *reinterpret_cast<const uint32_t*>(p + 8 * 40);
            ah[mi][2] = *reinterpret_cast<const uint32_t*>(p + 8);
            ah[mi][3] = *reinterpret_cast<const uint32_t*>(p + 8 * 40 + 8);
            const bf16* q = sAl + (wrow + mi * 16 + g) * 40 + ko + 2 * tig;
            al[mi][0] = *reinterpret_cast<const uint32_t*>(q);
            al[mi][1] = *reinterpret_cast<const uint32_t*>(q + 8 * 40);
            al[mi][2] = *reinterpret_cast<const uint32_t*>(q + 8);
            al[mi][3] = *reinterpret_cast<const uint32_t*>(q + 8 * 40 + 8);
        }
        uint32_t bhf[8][2], blf[8][2];
#pragma unroll
        for (int ni = 0; ni < 8; ++ni) {
            const bf16* p = sBh + (wcol + ni * 8 + g) * 40 + ko + 2 * tig;
            bhf[ni][0] = *reinterpret_cast<const uint32_t*>(p);
            bhf[ni][1] = *reinterpret_cast<const uint32_t*>(p + 8);
            const bf16* q = sBl + (wcol + ni * 8 + g) * 40 + ko + 2 * tig;
            blf[ni][0] = *reinterpret_cast<const uint32_t*>(q);
            blf[ni][1] = *reinterpret_cast<const uint32_t*>(q + 8);
        }
#pragma unroll
        for (int mi = 0; mi < 2; ++mi)
#pragma unroll
            for (int ni = 0; ni < 8; ++ni) {
                mma16816(acc[mi][ni], ah[mi], bhf[ni]);
                mma16816(acc[mi][ni], ah[mi], blf[ni]);
                mma16816(acc[mi][ni], al[mi], bhf[ni]);
            }
    }
}

// ---------------------------------------------------------------------------
// cp.async double-buffered GEMM mainloop over pre-split bf16 globals.
// smem: 2 stages x 4 tiles x (128 rows x 40 bf16) = 81920 B.
// ---------------------------------------------------------------------------
#define STAGE_ELEMS 20480   /* bf16 per stage (4 tiles x 5120) */
#define GEMM_SMEM (2 * STAGE_ELEMS * 2)

__device__ __forceinline__ void gemm_cp_main(
    const bf16* __restrict__ Ah, const bf16* __restrict__ Al,
    const bf16* __restrict__ Bh, const bf16* __restrict__ Bl,
    int mb, int nb, int tid, bf16* smem, float acc[2][8][4],
    int wrow, int wcol, int g, int tig)
{
    const uint32_t sbase = (uint32_t)__cvta_generic_to_shared(smem);

    auto issue = [&](int s, int kt) {
        const bf16* srcs[4] = {Ah, Al, Bh, Bl};
#pragma unroll
        for (int it = 0; it < 8; ++it) {
            const int tile = it >> 1;                 // compile-time
            int rem = (it & 1) * 256 + tid;           // 0..511
            int row = rem >> 2, c = rem & 3;
            int rb = (tile < 2) ? mb : nb;
            uint32_t sa = sbase +
                (uint32_t)((s * STAGE_ELEMS + tile * 5120 + row * 40 + c * 8) * 2);
            CP_ASYNC16(sa, &srcs[tile][(size_t)(rb + row) * DMODEL + kt + c * 8]);
        }
    };

    issue(0, 0);
    CP_COMMIT();
#pragma unroll 1
    for (int i = 0; i < 24; ++i) {
        if (i < 23) {
            issue((i + 1) & 1, (i + 1) * 32);
            CP_COMMIT();
            CP_WAIT_1();
        } else {
            CP_WAIT_0();
        }
        __syncthreads();
        bf16* st = smem + (i & 1) * STAGE_ELEMS;
        hmma_chunk(st, st + 5120, st + 10240, st + 15360,
                   wrow, wcol, g, tig, acc);
        __syncthreads();
    }
}

// ---------------------------------------------------------------------------
// QKV GEMM (cp.async): scatter fp32 q/k/v + bias
// ---------------------------------------------------------------------------
__global__ __launch_bounds__(256) void qkv_gemm_cp(const float* __restrict__ bias)
{
    extern __shared__ bf16 smem[];
    const int tid = threadIdx.x;
    const int wid = tid >> 5, lane = tid & 31;
    const int nb = blockIdx.x * 128, mb = blockIdx.y * 128;
    const int wrow = (wid & 3) * 32;
    const int wcol = (wid >> 2) * 64;
    const int g = lane >> 2, tig = lane & 3;

    float acc[2][8][4];
#pragma unroll
    for (int mi = 0; mi < 2; ++mi)
#pragma unroll
        for (int ni = 0; ni < 8; ++ni)
#pragma unroll
            for (int r = 0; r < 4; ++r) acc[mi][ni][r] = 0.f;

    gemm_cp_main(g_h_hi, g_h_lo, g_wqkvT_hi, g_wqkvT_lo,
                 mb, nb, tid, smem, acc, wrow, wcol, g, tig);

#pragma unroll
    for (int mi = 0; mi < 2; ++mi)
#pragma unroll
        for (int ni = 0; ni < 8; ++ni) {
            int col = nb + wcol + ni * 8 + 2 * tig;
            int which = col / DMODEL;
            int rem = col - which * DMODEL;
            int h = rem >> 6, d = rem & 63;
            float* dst = (which == 0) ? g_q : ((which == 1) ? g_k : g_v);
            float b0 = bias[col], b1 = bias[col + 1];
#pragma unroll
            for (int half = 0; half < 2; ++half) {
                int m = mb + wrow + mi * 16 + g + half * 8;
                int bb = m >> 10, s = m & 1023;
                float2 o = make_float2(acc[mi][ni][half * 2 + 0] + b0,
                                       acc[mi][ni][half * 2 + 1] + b1);
                *reinterpret_cast<float2*>(
                    &dst[(((size_t)(bb * NH + h) * SEQ + s) * HD) + d]) = o;
            }
        }
}

// ---------------------------------------------------------------------------
// Proj GEMM (cp.async): ctx (pre-split, row-major) @ wprojT + bias -> out
// ---------------------------------------------------------------------------
__global__ __launch_bounds__(256) void proj_gemm_cp(
    const float* __restrict__ bias, float* __restrict__ out)
{
    extern __shared__ bf16 smem[];
    const int tid = threadIdx.x;
    const int wid = tid >> 5, lane = tid & 31;
    const int nb = blockIdx.x * 128, mb = blockIdx.y * 128;
    const int wrow = (wid & 3) * 32;
    const int wcol = (wid >> 2) * 64;
    const int g = lane >> 2, tig = lane & 3;

    float acc[2][8][4];
#pragma unroll
    for (int mi = 0; mi < 2; ++mi)
#pragma unroll
        for (int ni = 0; ni < 8; ++ni)
#pragma unroll
            for (int r = 0; r < 4; ++r) acc[mi][ni][r] = 0.f;

    gemm_cp_main(g_ctx_hi, g_ctx_lo, g_wprojT_hi, g_wprojT_lo,
                 mb, nb, tid, smem, acc, wrow, wcol, g, tig);

#pragma unroll
    for (int mi = 0; mi < 2; ++mi)
#pragma unroll
        for (int ni = 0; ni < 8; ++ni) {
            int col = nb + wcol + ni * 8 + 2 * tig;
            float b0 = bias[col], b1 = bias[col + 1];
#pragma unroll
            for (int half = 0; half < 2; ++half) {
                int row = mb + wrow + mi * 16 + g + half * 8;
                float2 o = make_float2(acc[mi][ni][half * 2 + 0] + b0,
                                       acc[mi][ni][half * 2 + 1] + b1);
                *reinterpret_cast<float2*>(&out[(size_t)row * DMODEL + col]) = o;
            }
        }
}

// ---------------------------------------------------------------------------
// Flash attention (R15 mainloop; epilogue writes pre-split ctx [m][768])
// ---------------------------------------------------------------------------
#define ATTN_SMEM 94208

__global__ __launch_bounds__(256) void attn_hmma()
{
    extern __shared__ char sm[];
    bf16* sQh = (bf16*)(sm + 0);
    bf16* sQl = (bf16*)(sm + 18432);
    bf16* sKVh = (bf16*)(sm + 36864);
    bf16* sKVl = (bf16*)(sm + 46080);
    uint32_t* sPh = (uint32_t*)(sm + 55296);
    uint32_t* sPl = (uint32_t*)(sm + 73728);
    float* sMax = (float*)(sm + 92160);
    float* sSum = (float*)(sm + 93184);

    const int tid = threadIdx.x;
    const int wid = tid >> 5, lane = tid & 31;
    const int qb = blockIdx.x * 128;
    const int h = blockIdx.y, b = blockIdx.z;
    const size_t base = ((size_t)(b * NH + h)) * SEQ * HD;
    const float* Qg = g_q + base;
    const float* Kg = g_k + base;
    const float* Vg = g_v + base;

    const int wrow = (wid & 3) * 32;
    const int kvh = wid >> 2;
    const int wcol = kvh * 32;
    const int g = lane >> 2, tig = lane & 3;

#pragma unroll
    for (int it = 0; it < 8; ++it) {
        int id = it * 256 + tid;
        int row = id >> 4, c = id & 15;
        float4 v = *reinterpret_cast<const float4*>(
            &Qg[(size_t)(qb + row) * HD + c * 4]);
        __nv_bfloat162 h0, l0, h1, l1;
        split2(v.x, v.y, h0, l0);
        split2(v.z, v.w, h1, l1);
        *reinterpret_cast<__nv_bfloat162*>(&sQh[row * 72 + c * 4]) = h0;
        *reinterpret_cast<__nv_bfloat162*>(&sQh[row * 72 + c * 4 + 2]) = h1;
        *reinterpret_cast<__nv_bfloat162*>(&sQl[row * 72 + c * 4]) = l0;
        *reinterpret_cast<__nv_bfloat162*>(&sQl[row * 72 + c * 4 + 2]) = l1;
    }

    float oacc[2][4][4];
#pragma unroll
    for (int mi = 0; mi < 2; ++mi)
#pragma unroll
        for (int ni = 0; ni < 4; ++ni)
#pragma unroll
            for (int r = 0; r < 4; ++r) oacc[mi][ni][r] = 0.f;
    float m_run[2][2] = {{-1e30f, -1e30f}, {-1e30f, -1e30f}};
    float l_run[2][2] = {{0.f, 0.f}, {0.f, 0.f}};

    for (int kt = 0; kt < SEQ; kt += 64) {
#pragma unroll
        for (int it = 0; it < 4; ++it) {
            int id = it * 256 + tid;
            int j = id >> 4, c = id & 15;
            float4 v = *reinterpret_cast<const float4*>(
                &Kg[(size_t)(kt + j) * HD + c * 4]);
            __nv_bfloat162 h0, l0, h1, l1;
            split2(v.x, v.y, h0, l0);
            split2(v.z, v.w, h1, l1);
            *reinterpret_cast<__nv_bfloat162*>(&sKVh[j * 72 + c * 4]) = h0;
            *reinterpret_cast<__nv_bfloat162*>(&sKVh[j * 72 + c * 4 + 2]) = h1;
            *reinterpret_cast<__nv_bfloat162*>(&sKVl[j * 72 + c * 4]) = l0;
            *reinterpret_cast<__nv_bfloat162*>(&sKVl[j * 72 + c * 4 + 2]) = l1;
        }
        __syncthreads();

        float sacc[2][4][4];
#pragma unroll
        for (int mi = 0; mi < 2; ++mi)
#pragma unroll
            for (int ni = 0; ni < 4; ++ni)
#pragma unroll
                for (int r = 0; r < 4; ++r) sacc[mi][ni][r] = 0.f;

#pragma unroll
        for (int ks = 0; ks < 4; ++ks) {
            const int ko = ks * 16;
            uint32_t ah[2][4], al[2][4];
#pragma unroll
            for (int mi = 0; mi < 2; ++mi) {
                const bf16* p = sQh + (wrow + mi * 16 + g) * 72 + ko + 2 * tig;
                ah[mi][0] = *reinterpret_cast<const uint32_t*>(p);
                ah[mi][1] = *reinterpret_cast<const uint32_t*>(p + 8 * 72);
                ah[mi][2] = *reinterpret_cast<const uint32_t*>(p + 8);
                ah[mi][3] = *reinterpret_cast<const uint32_t*>(p + 8 * 72 + 8);
                const bf16* q = sQl + (wrow + mi * 16 + g) * 72 + ko + 2 * tig;
                al[mi][0] = *reinterpret_cast<const uint32_t*>(q);
                al[mi][1] = *reinterpret_cast<const uint32_t*>(q + 8 * 72);
                al[mi][2] = *reinterpret_cast<const uint32_t*>(q + 8);
                al[mi][3] = *reinterpret_cast<const uint32_t*>(q + 8 * 72 + 8);
            }
            uint32_t bhf[4][2], blf[4][2];
#pragma unroll
            for (int ni = 0; ni < 4; ++ni) {
                const bf16* p = sKVh + (wcol + ni * 8 + g) * 72 + ko + 2 * tig;
                bhf[ni][0] = *reinterpret_cast<const uint32_t*>(p);
                bhf[ni][1] = *reinterpret_cast<const uint32_t*>(p + 8);
                const bf16* q = sKVl + (wcol + ni * 8 + g) * 72 + ko + 2 * tig;
                blf[ni][0] = *reinterpret_cast<const uint32_t*>(q);
                blf[ni][1] = *reinterpret_cast<const uint32_t*>(q + 8);
            }
#pragma unroll
            for (int mi = 0; mi < 2; ++mi)
#pragma unroll
                for (int ni = 0; ni < 4; ++ni) {
                    mma16816(sacc[mi][ni], ah[mi], bhf[ni]);
                    mma16816(sacc[mi][ni], ah[mi], blf[ni]);
                    mma16816(sacc[mi][ni], al[mi], bhf[ni]);
                }
        }

#pragma unroll
        for (int mi = 0; mi < 2; ++mi)
#pragma unroll
            for (int half = 0; half < 2; ++half) {
                float pm = -1e30f;
#pragma unroll
                for (int ni = 0; ni < 4; ++ni) {
                    pm = fmaxf(pm, sacc[mi][ni][half * 2 + 0]);
                    pm = fmaxf(pm, sacc[mi][ni][half * 2 + 1]);
                }
                pm = fmaxf(pm, __shfl_xor_sync(0xffffffffu, pm, 1));
                pm = fmaxf(pm, __shfl_xor_sync(0xffffffffu, pm, 2));
                int row = wrow + mi * 16 + half * 8 + g;
                sMax[row * 2 + kvh] = pm;
            }
        __syncthreads();

        float alpha[2][2];
#pragma unroll
        for (int mi = 0; mi < 2; ++mi)
#pragma unroll
            for (int half = 0; half < 2; ++half) {
                int row = wrow + mi * 16 + half * 8 + g;
                float mt = fmaxf(sMax[row * 2], sMax[row * 2 + 1]) * ATTN_SCALE;
                float mnew = fmaxf(m_run[mi][half], mt);
                alpha[mi][half] = __expf(m_run[mi][half] - mnew);
                m_run[mi][half] = mnew;
            }
#pragma unroll
        for (int mi = 0; mi < 2; ++mi)
#pragma unroll
            for (int ni = 0; ni < 4; ++ni)
#pragma unroll
                for (int r = 0; r < 4; ++r)
                    sacc[mi][ni][r] = __expf(
                        fmaf(sacc[mi][ni][r], ATTN_SCALE, -m_run[mi][r >> 1]));

#pragma unroll
        for (int mi = 0; mi < 2; ++mi)
#pragma unroll
            for (int half = 0; half < 2; ++half) {
                float ps = 0.f;
#pragma unroll
                for (int ni = 0; ni < 4; ++ni)
                    ps += sacc[mi][ni][half * 2 + 0] + sacc[mi][ni][half * 2 + 1];
                ps += __shfl_xor_sync(0xffffffffu, ps, 1);
                ps += __shfl_xor_sync(0xffffffffu, ps, 2);
                int row = wrow + mi * 16 + half * 8 + g;
                sSum[row * 2 + kvh] = ps;
            }

#pragma unroll
        for (int mi = 0; mi < 2; ++mi)
#pragma unroll
            for (int ni = 0; ni < 4; ++ni) {
                int row0 = wrow + mi * 16 + g;
                int idx = kvh * 16 + ni * 4 + tig;
                __nv_bfloat162 hh, ll;
                split2(sacc[mi][ni][0], sacc[mi][ni][1], hh, ll);
                sPh[row0 * 36 + idx] = *reinterpret_cast<uint32_t*>(&hh);
                sPl[row0 * 36 + idx] = *reinterpret_cast<uint32_t*>(&ll);
                split2(sacc[mi][ni][2], sacc[mi][ni][3], hh, ll);
                sPh[(row0 + 8) * 36 + idx] = *reinterpret_cast<uint32_t*>(&hh);
                sPl[(row0 + 8) * 36 + idx] = *reinterpret_cast<uint32_t*>(&ll);
            }

#pragma unroll
        for (int it = 0; it < 4; ++it) {
            int id = it * 256 + tid;
            int j = id >> 4, c = id & 15;
            float4 v = *reinterpret_cast<const float4*>(
                &Vg[(size_t)(kt + j) * HD + c * 4]);
            int d = c * 4;
            bf16 h0 = __float2bfloat16(v.x), h1 = __float2bfloat16(v.y);
            bf16 h2 = __float2bfloat16(v.z), h3 = __float2bfloat16(v.w);
            sKVh[(d + 0) * 72 + j] = h0;
            sKVh[(d + 1) * 72 + j] = h1;
            sKVh[(d + 2) * 72 + j] = h2;
            sKVh[(d + 3) * 72 + j] = h3;
            sKVl[(d + 0) * 72 + j] = __float2bfloat16(v.x - __bfloat162float(h0));
            sKVl[(d + 1) * 72 + j] = __float2bfloat16(v.y - __bfloat162float(h1));
            sKVl[(d + 2) * 72 + j] = __float2bfloat16(v.z - __bfloat162float(h2));
            sKVl[(d + 3) * 72 + j] = __float2bfloat16(v.w - __bfloat162float(h3));
        }
        __syncthreads();

#pragma unroll
        for (int mi = 0; mi < 2; ++mi)
#pragma unroll
            for (int half = 0; half < 2; ++half) {
                int row = wrow + mi * 16 + half * 8 + g;
                float st = sSum[row * 2] + sSum[row * 2 + 1];
                l_run[mi][half] = fmaf(l_run[mi][half], alpha[mi][half], st);
            }
#pragma unroll
        for (int mi = 0; mi < 2; ++mi)
#pragma unroll
            for (int ni = 0; ni < 4; ++ni)
#pragma unroll
                for (int r = 0; r < 4; ++r)
                    oacc[mi][ni][r] *= alpha[mi][r >> 1];

#pragma unroll
        for (int ks = 0; ks < 4; ++ks) {
            uint32_t pah[2][4], pal[2][4];
#pragma unroll
            for (int mi = 0; mi < 2; ++mi) {
                int bidx = (wrow + mi * 16 + g) * 36 + ks * 8 + tig;
                pah[mi][0] = sPh[bidx];
                pah[mi][1] = sPh[bidx + 8 * 36];
                pah[mi][2] = sPh[bidx + 4];
                pah[mi][3] = sPh[bidx + 8 * 36 + 4];
                pal[mi][0] = sPl[bidx];
                pal[mi][1] = sPl[bidx + 8 * 36];
                pal[mi][2] = sPl[bidx + 4];
                pal[mi][3] = sPl[bidx + 8 * 36 + 4];
            }
            uint32_t vbh[4][2], vbl[4][2];
#pragma unroll
            for (int ni = 0; ni < 4; ++ni) {
                const bf16* p = sKVh + (wcol + ni * 8 + g) * 72 + ks * 16 + 2 * tig;
                vbh[ni][0] = *reinterpret_cast<const uint32_t*>(p);
                vbh[ni][1] = *reinterpret_cast<const uint32_t*>(p + 8);
                const bf16* q = sKVl + (wcol + ni * 8 + g) * 72 + ks * 16 + 2 * tig;
                vbl[ni][0] = *reinterpret_cast<const uint32_t*>(q);
                vbl[ni][1] = *reinterpret_cast<const uint32_t*>(q + 8);
            }
#pragma unroll
            for (int mi = 0; mi < 2; ++mi)
#pragma unroll
                for (int ni = 0; ni < 4; ++ni) {
                    mma16816(oacc[mi][ni], pah[mi], vbh[ni]);
                    mma16816(oacc[mi][ni], pah[mi], vbl[ni]);
                    mma16816(oacc[mi][ni], pal[mi], vbh[ni]);
                }
        }
        __syncthreads();
    }

    // ---- Epilogue: normalize and store pre-split ctx [m][768] ----
#pragma unroll
    for (int mi = 0; mi < 2; ++mi) {
        int r0 = wrow + mi * 16 + g;
        float inv0 = 1.f / l_run[mi][0];
        float inv1 = 1.f / l_run[mi][1];
#pragma unroll
        for (int ni = 0; ni < 4; ++ni) {
            int col = wcol + ni * 8 + 2 * tig;
            size_t o0 = (size_t)(b * SEQ + qb + r0) * DMODEL + h * HD + col;
            size_t o1 = (size_t)(b * SEQ + qb + r0 + 8) * DMODEL + h * HD + col;
            __nv_bfloat162 hh, ll;
            split2(oacc[mi][ni][0] * inv0, oacc[mi][ni][1] * inv0, hh, ll);
            *reinterpret_cast<__nv_bfloat162*>(&g_ctx_hi[o0]) = hh;
            *reinterpret_cast<__nv_bfloat162*>(&g_ctx_lo[o0]) = ll;
            split2(oacc[mi][ni][2] * inv1, oacc[mi][ni][3] * inv1, hh, ll);
            *reinterpret_cast<__nv_bfloat162*>(&g_ctx_hi[o1]) = hh;
            *reinterpret_cast<__nv_bfloat162*>(&g_ctx_lo[o1]) = ll;
        }
    }
}

// ---------------------------------------------------------------------------
extern "C" void kernel_launch(void* const* d_in, const int* in_sizes, int n_in,
                              void* d_out, int out_size)
{
    const float* hidden = (const float*)d_in[0];
    const float* w_qkv  = (const float*)d_in[1];
    const float* b_qkv  = (const float*)d_in[2];
    const float* w_proj = (const float*)d_in[3];
    const float* b_proj = (const float*)d_in[4];
    float* out = (float*)d_out;

    cudaFuncSetAttribute(attn_hmma,
                         cudaFuncAttributeMaxDynamicSharedMemorySize, ATTN_SMEM);
    cudaFuncSetAttribute(qkv_gemm_cp,
                         cudaFuncAttributeMaxDynamicSharedMemorySize, GEMM_SMEM);
    cudaFuncSetAttribute(proj_gemm_cp,
                         cudaFuncAttributeMaxDynamicSharedMemorySize, GEMM_SMEM);

    conv_hidden<<<(MTOT * DMODEL / 4) / 256, 256>>>(hidden);
    transpose_wqkv<<<dim3(NQKV / 32, DMODEL / 32), dim3(32, 8)>>>(w_qkv);
    transpose_wproj<<<dim3(DMODEL / 32, DMODEL / 32), dim3(32, 8)>>>(w_proj);

    qkv_gemm_cp<<<dim3(NQKV / 128, MTOT / 128), 256, GEMM_SMEM>>>(b_qkv);
    attn_hmma<<<dim3(SEQ / 128, NH, BATCH), 256, ATTN_SMEM>>>();
    proj_gemm_cp<<<dim3(DMODEL / 128, MTOT / 128), 256, GEMM_SMEM>>>(b_proj, out);
}

// round 17
// speedup vs baseline: 5.7127x; 1.0317x over previous
#include <cuda_runtime.h>
#include <cuda_bf16.h>
#include <math.h>
#include <stdint.h>

#define BATCH 8
#define SEQ 1024
#define DMODEL 768
#define NH 12
#define HD 64
#define ATTN_SCALE 0.125f
#define MTOT (BATCH * SEQ)         /* 8192 */
#define NQKV (3 * DMODEL)          /* 2304 */

typedef __nv_bfloat16 bf16;

// ---------------------------------------------------------------------------
// Scratch — referenced ONLY from device code (GB300 ATS pitfall: host-side
// __device__ symbol addresses silently route to host-shadow memory).
// q/k/v now pre-split bf16 hi/lo in [head][s][d] layout.
// ---------------------------------------------------------------------------
__device__ __align__(16) bf16 g_q_hi[BATCH * NH * SEQ * HD];
__device__ __align__(16) bf16 g_q_lo[BATCH * NH * SEQ * HD];
__device__ __align__(16) bf16 g_k_hi[BATCH * NH * SEQ * HD];
__device__ __align__(16) bf16 g_k_lo[BATCH * NH * SEQ * HD];
__device__ __align__(16) bf16 g_v_hi[BATCH * NH * SEQ * HD];
__device__ __align__(16) bf16 g_v_lo[BATCH * NH * SEQ * HD];

__device__ __align__(16) bf16 g_h_hi[MTOT * DMODEL];
__device__ __align__(16) bf16 g_h_lo[MTOT * DMODEL];
__device__ __align__(16) bf16 g_wqkvT_hi[NQKV * DMODEL];    // [N][K]
__device__ __align__(16) bf16 g_wqkvT_lo[NQKV * DMODEL];
__device__ __align__(16) bf16 g_wprojT_hi[DMODEL * DMODEL]; // [N][K]
__device__ __align__(16) bf16 g_wprojT_lo[DMODEL * DMODEL];
__device__ __align__(16) bf16 g_ctx_hi[MTOT * DMODEL];      // [m][768]
__device__ __align__(16) bf16 g_ctx_lo[MTOT * DMODEL];

// ---------------------------------------------------------------------------
// Helpers
// ---------------------------------------------------------------------------
__device__ __forceinline__ void mma16816(float* c, const uint32_t* a,
                                         const uint32_t* b) {
    asm volatile(
        "mma.sync.aligned.m16n8k16.row.col.f32.bf16.bf16.f32 "
        "{%0,%1,%2,%3}, {%4,%5,%6,%7}, {%8,%9}, {%0,%1,%2,%3};"
        : "+f"(c[0]), "+f"(c[1]), "+f"(c[2]), "+f"(c[3])
        : "r"(a[0]), "r"(a[1]), "r"(a[2]), "r"(a[3]), "r"(b[0]), "r"(b[1]));
}

__device__ __forceinline__ void split2(float v0, float v1,
                                       __nv_bfloat162& h, __nv_bfloat162& l) {
    bf16 h0 = __float2bfloat16(v0), h1 = __float2bfloat16(v1);
    h = __halves2bfloat162(h0, h1);
    l = __halves2bfloat162(__float2bfloat16(v0 - __bfloat162float(h0)),
                           __float2bfloat16(v1 - __bfloat162float(h1)));
}

#define CP_ASYNC16(saddr, gptr) \
    asm volatile("cp.async.cg.shared.global [%0], [%1], 16;" \
                 :: "r"(saddr), "l"(gptr) : "memory")
#define CP_COMMIT() asm volatile("cp.async.commit_group;" ::: "memory")
#define CP_WAIT_1() asm volatile("cp.async.wait_group 1;" ::: "memory")
#define CP_WAIT_0() asm volatile("cp.async.wait_group 0;" ::: "memory")

// ---------------------------------------------------------------------------
// Pre-split converters
// ---------------------------------------------------------------------------
__global__ __launch_bounds__(256) void conv_hidden(const float* __restrict__ src)
{
    int i = blockIdx.x * 256 + threadIdx.x;
    float4 v = reinterpret_cast<const float4*>(src)[i];
    __nv_bfloat162 h0, l0, h1, l1;
    split2(v.x, v.y, h0, l0);
    split2(v.z, v.w, h1, l1);
    int o = i * 4;
    *reinterpret_cast<__nv_bfloat162*>(&g_h_hi[o]) = h0;
    *reinterpret_cast<__nv_bfloat162*>(&g_h_hi[o + 2]) = h1;
    *reinterpret_cast<__nv_bfloat162*>(&g_h_lo[o]) = l0;
    *reinterpret_cast<__nv_bfloat162*>(&g_h_lo[o + 2]) = l1;
}

__device__ __forceinline__ void tsplit_body(
    const float* __restrict__ W, bf16* __restrict__ WTh,
    bf16* __restrict__ WTl, int N, int K)
{
    __shared__ float t[32][33];
    int n0 = blockIdx.x * 32, k0 = blockIdx.y * 32;
    int tx = threadIdx.x, ty = threadIdx.y;
#pragma unroll
    for (int i = 0; i < 4; ++i)
        t[ty + i * 8][tx] = W[(size_t)(k0 + ty + i * 8) * N + n0 + tx];
    __syncthreads();
#pragma unroll
    for (int i = 0; i < 4; ++i) {
        int n = ty + i * 8;
        float v = t[tx][n];
        bf16 h = __float2bfloat16(v);
        size_t o = (size_t)(n0 + n) * K + k0 + tx;
        WTh[o] = h;
        WTl[o] = __float2bfloat16(v - __bfloat162float(h));
    }
}

__global__ void transpose_wqkv(const float* __restrict__ W)
{
    tsplit_body(W, g_wqkvT_hi, g_wqkvT_lo, NQKV, DMODEL);
}

__global__ void transpose_wproj(const float* __restrict__ W)
{
    tsplit_body(W, g_wprojT_hi, g_wprojT_lo, DMODEL, DMODEL);
}

// ---------------------------------------------------------------------------
// Shared HMMA compute for one staged 32-k chunk (bf16 hi/lo smem, stride 40).
// ---------------------------------------------------------------------------
__device__ __forceinline__ void hmma_chunk(
    const bf16* sAh, const bf16* sAl, const bf16* sBh, const bf16* sBl,
    int wrow, int wcol, int g, int tig, float acc[2][8][4])
{
#pragma unroll
    for (int ks = 0; ks < 2; ++ks) {
        const int ko = ks * 16;
        uint32_t ah[2][4], al[2][4];
#pragma unroll
        for (int mi = 0; mi < 2; ++mi) {
            const bf16* p = sAh + (wrow + mi * 16 + g) * 40 + ko + 2 * tig;
            ah[mi][0] = *reinterpret_cast<const uint32_t*>(p);
            ah[mi][1] = *reinterpret_cast<const uint32_t*>(p + 8 * 40);
            ah[mi][2] = *reinterpret_cast<const uint32_t*>(p + 8);
            ah[mi][3] = *reinterpret_cast<const uint32_t*>(p + 8 * 40 + 8);
            const bf16* q = sAl + (wrow + mi * 16 + g) * 40 + ko + 2 * tig;
            al[mi][0] = *reinterpret_cast<const uint32_t*>(q);
            al[mi][1] = *reinterpret_cast<const uint32_t*>(q + 8 * 40);
            al[mi][2] = *reinterpret_cast<const uint32_t*>(q + 8);
            al[mi][3] = *reinterpret_cast<const uint32_t*>(q + 8 * 40 + 8);
        }
        uint32_t bhf[8][2], blf[8][2];
#pragma unroll
        for (int ni = 0; ni < 8; ++ni) {
            const bf16* p = sBh + (wcol + ni * 8 + g) * 40 + ko + 2 * tig;
            bhf[ni][0] = *reinterpret_cast<const uint32_t*>(p);
            bhf[ni][1] = *reinterpret_cast<const uint32_t*>(p + 8);
            const bf16* q = sBl + (wcol + ni * 8 + g) * 40 + ko + 2 * tig;
            blf[ni][0] = *reinterpret_cast<const uint32_t*>(q);
            blf[ni][1] = *reinterpret_cast<const uint32_t*>(q + 8);
        }
#pragma unroll
        for (int mi = 0; mi < 2; ++mi)
#pragma unroll
            for (int ni = 0; ni < 8; ++ni) {
                mma16816(acc[mi][ni], ah[mi], bhf[ni]);
                mma16816(acc[mi][ni], ah[mi], blf[ni]);
                mma16816(acc[mi][ni], al[mi], bhf[ni]);
            }
    }
}

// ---------------------------------------------------------------------------
// cp.async double-buffered GEMM mainloop over pre-split bf16 globals.
// ---------------------------------------------------------------------------
#define STAGE_ELEMS 20480
#define GEMM_SMEM (2 * STAGE_ELEMS * 2)

__device__ __forceinline__ void gemm_cp_main(
    const bf16* __restrict__ Ah, const bf16* __restrict__ Al,
    const bf16* __restrict__ Bh, const bf16* __restrict__ Bl,
    int mb, int nb, int tid, bf16* smem, float acc[2][8][4],
    int wrow, int wcol, int g, int tig)
{
    const uint32_t sbase = (uint32_t)__cvta_generic_to_shared(smem);

    auto issue = [&](int s, int kt) {
        const bf16* srcs[4] = {Ah, Al, Bh, Bl};
#pragma unroll
        for (int it = 0; it < 8; ++it) {
            const int tile = it >> 1;
            int rem = (it & 1) * 256 + tid;
            int row = rem >> 2, c = rem & 3;
            int rb = (tile < 2) ? mb : nb;
            uint32_t sa = sbase +
                (uint32_t)((s * STAGE_ELEMS + tile * 5120 + row * 40 + c * 8) * 2);
            CP_ASYNC16(sa, &srcs[tile][(size_t)(rb + row) * DMODEL + kt + c * 8]);
        }
    };

    issue(0, 0);
    CP_COMMIT();
#pragma unroll 1
    for (int i = 0; i < 24; ++i) {
        if (i < 23) {
            issue((i + 1) & 1, (i + 1) * 32);
            CP_COMMIT();
            CP_WAIT_1();
        } else {
            CP_WAIT_0();
        }
        __syncthreads();
        bf16* st = smem + (i & 1) * STAGE_ELEMS;
        hmma_chunk(st, st + 5120, st + 10240, st + 15360,
                   wrow, wcol, g, tig, acc);
        __syncthreads();
    }
}

// ---------------------------------------------------------------------------
// QKV GEMM (cp.async, 2 CTAs/SM): epilogue splits and stores q/k/v hi/lo
// ---------------------------------------------------------------------------
__global__ __launch_bounds__(256, 2) void qkv_gemm_cp(const float* __restrict__ bias)
{
    extern __shared__ bf16 smem[];
    const int tid = threadIdx.x;
    const int wid = tid >> 5, lane = tid & 31;
    const int nb = blockIdx.x * 128, mb = blockIdx.y * 128;
    const int wrow = (wid & 3) * 32;
    const int wcol = (wid >> 2) * 64;
    const int g = lane >> 2, tig = lane & 3;

    float acc[2][8][4];
#pragma unroll
    for (int mi = 0; mi < 2; ++mi)
#pragma unroll
        for (int ni = 0; ni < 8; ++ni)
#pragma unroll
            for (int r = 0; r < 4; ++r) acc[mi][ni][r] = 0.f;

    gemm_cp_main(g_h_hi, g_h_lo, g_wqkvT_hi, g_wqkvT_lo,
                 mb, nb, tid, smem, acc, wrow, wcol, g, tig);

#pragma unroll
    for (int mi = 0; mi < 2; ++mi)
#pragma unroll
        for (int ni = 0; ni < 8; ++ni) {
            int col = nb + wcol + ni * 8 + 2 * tig;
            int which = col / DMODEL;
            int rem = col - which * DMODEL;
            int h = rem >> 6, d = rem & 63;
            bf16* dh = (which == 0) ? g_q_hi : ((which == 1) ? g_k_hi : g_v_hi);
            bf16* dl = (which == 0) ? g_q_lo : ((which == 1) ? g_k_lo : g_v_lo);
            float b0 = bias[col], b1 = bias[col + 1];
#pragma unroll
            for (int half = 0; half < 2; ++half) {
                int m = mb + wrow + mi * 16 + g + half * 8;
                int bb = m >> 10, s = m & 1023;
                __nv_bfloat162 hh, ll;
                split2(acc[mi][ni][half * 2 + 0] + b0,
                       acc[mi][ni][half * 2 + 1] + b1, hh, ll);
                size_t idx = (((size_t)(bb * NH + h) * SEQ + s) * HD) + d;
                *reinterpret_cast<__nv_bfloat162*>(&dh[idx]) = hh;
                *reinterpret_cast<__nv_bfloat162*>(&dl[idx]) = ll;
            }
        }
}

// ---------------------------------------------------------------------------
// Proj GEMM (cp.async, control: natural occupancy)
// ---------------------------------------------------------------------------
__global__ __launch_bounds__(256) void proj_gemm_cp(
    const float* __restrict__ bias, float* __restrict__ out)
{
    extern __shared__ bf16 smem[];
    const int tid = threadIdx.x;
    const int wid = tid >> 5, lane = tid & 31;
    const int nb = blockIdx.x * 128, mb = blockIdx.y * 128;
    const int wrow = (wid & 3) * 32;
    const int wcol = (wid >> 2) * 64;
    const int g = lane >> 2, tig = lane & 3;

    float acc[2][8][4];
#pragma unroll
    for (int mi = 0; mi < 2; ++mi)
#pragma unroll
        for (int ni = 0; ni < 8; ++ni)
#pragma unroll
            for (int r = 0; r < 4; ++r) acc[mi][ni][r] = 0.f;

    gemm_cp_main(g_ctx_hi, g_ctx_lo, g_wprojT_hi, g_wprojT_lo,
                 mb, nb, tid, smem, acc, wrow, wcol, g, tig);

#pragma unroll
    for (int mi = 0; mi < 2; ++mi)
#pragma unroll
        for (int ni = 0; ni < 8; ++ni) {
            int col = nb + wcol + ni * 8 + 2 * tig;
            float b0 = bias[col], b1 = bias[col + 1];
#pragma unroll
            for (int half = 0; half < 2; ++half) {
                int row = mb + wrow + mi * 16 + g + half * 8;
                float2 o = make_float2(acc[mi][ni][half * 2 + 0] + b0,
                                       acc[mi][ni][half * 2 + 1] + b1);
                *reinterpret_cast<float2*>(&out[(size_t)row * DMODEL + col]) = o;
            }
        }
}

// ---------------------------------------------------------------------------
// Flash attention: cp.async staging from pre-split q/k; V transpose-scatter
// from pre-split v. MMA/softmax identical to R15.
// ---------------------------------------------------------------------------
#define ATTN_SMEM 94208

__global__ __launch_bounds__(256) void attn_hmma()
{
    extern __shared__ char sm[];
    bf16* sQh = (bf16*)(sm + 0);
    bf16* sQl = (bf16*)(sm + 18432);
    bf16* sKVh = (bf16*)(sm + 36864);
    bf16* sKVl = (bf16*)(sm + 46080);
    uint32_t* sPh = (uint32_t*)(sm + 55296);
    uint32_t* sPl = (uint32_t*)(sm + 73728);
    float* sMax = (float*)(sm + 92160);
    float* sSum = (float*)(sm + 93184);
    const uint32_t smbase = (uint32_t)__cvta_generic_to_shared(sm);

    const int tid = threadIdx.x;
    const int wid = tid >> 5, lane = tid & 31;
    const int qb = blockIdx.x * 128;
    const int h = blockIdx.y, b = blockIdx.z;
    const size_t base = ((size_t)(b * NH + h)) * SEQ * HD;

    const int wrow = (wid & 3) * 32;
    const int kvh = wid >> 2;
    const int wcol = kvh * 32;
    const int g = lane >> 2, tig = lane & 3;

    // ---- Stage Q once via cp.async (hi/lo, stride 72) ----
#pragma unroll
    for (int it = 0; it < 8; ++it) {
        int id = it * 256 + tid;          // 0..2047
        int row = id >> 4, rem = id & 15;
        int arr = rem >> 3, c = rem & 7;
        const bf16* src = (arr ? g_q_lo : g_q_hi) + base +
                          (size_t)(qb + row) * HD + c * 8;
        uint32_t dst = smbase + (uint32_t)(arr * 18432 + (row * 72 + c * 8) * 2);
        CP_ASYNC16(dst, src);
    }
    CP_COMMIT();

    float oacc[2][4][4];
#pragma unroll
    for (int mi = 0; mi < 2; ++mi)
#pragma unroll
        for (int ni = 0; ni < 4; ++ni)
#pragma unroll
            for (int r = 0; r < 4; ++r) oacc[mi][ni][r] = 0.f;
    float m_run[2][2] = {{-1e30f, -1e30f}, {-1e30f, -1e30f}};
    float l_run[2][2] = {{0.f, 0.f}, {0.f, 0.f}};

    for (int kt = 0; kt < SEQ; kt += 64) {
        // ---- Stage K tile via cp.async ----
#pragma unroll
        for (int it = 0; it < 4; ++it) {
            int id = it * 256 + tid;      // 0..1023
            int j = id >> 4, rem = id & 15;
            int arr = rem >> 3, c = rem & 7;
            const bf16* src = (arr ? g_k_lo : g_k_hi) + base +
                              (size_t)(kt + j) * HD + c * 8;
            uint32_t dst = smbase +
                (uint32_t)(36864 + arr * 9216 + (j * 72 + c * 8) * 2);
            CP_ASYNC16(dst, src);
        }
        CP_COMMIT();
        CP_WAIT_0();
        __syncthreads();

        // ---- S = Q K^T ----
        float sacc[2][4][4];
#pragma unroll
        for (int mi = 0; mi < 2; ++mi)
#pragma unroll
            for (int ni = 0; ni < 4; ++ni)
#pragma unroll
                for (int r = 0; r < 4; ++r) sacc[mi][ni][r] = 0.f;

#pragma unroll
        for (int ks = 0; ks < 4; ++ks) {
            const int ko = ks * 16;
            uint32_t ah[2][4], al[2][4];
#pragma unroll
            for (int mi = 0; mi < 2; ++mi) {
                const bf16* p = sQh + (wrow + mi * 16 + g) * 72 + ko + 2 * tig;
                ah[mi][0] = *reinterpret_cast<const uint32_t*>(p);
                ah[mi][1] = *reinterpret_cast<const uint32_t*>(p + 8 * 72);
                ah[mi][2] = *reinterpret_cast<const uint32_t*>(p + 8);
                ah[mi][3] = *reinterpret_cast<const uint32_t*>(p + 8 * 72 + 8);
                const bf16* q = sQl + (wrow + mi * 16 + g) * 72 + ko + 2 * tig;
                al[mi][0] = *reinterpret_cast<const uint32_t*>(q);
                al[mi][1] = *reinterpret_cast<const uint32_t*>(q + 8 * 72);
                al[mi][2] = *reinterpret_cast<const uint32_t*>(q + 8);
                al[mi][3] = *reinterpret_cast<const uint32_t*>(q + 8 * 72 + 8);
            }
            uint32_t bhf[4][2], blf[4][2];
#pragma unroll
            for (int ni = 0; ni < 4; ++ni) {
                const bf16* p = sKVh + (wcol + ni * 8 + g) * 72 + ko + 2 * tig;
                bhf[ni][0] = *reinterpret_cast<const uint32_t*>(p);
                bhf[ni][1] = *reinterpret_cast<const uint32_t*>(p + 8);
                const bf16* q = sKVl + (wcol + ni * 8 + g) * 72 + ko + 2 * tig;
                blf[ni][0] = *reinterpret_cast<const uint32_t*>(q);
                blf[ni][1] = *reinterpret_cast<const uint32_t*>(q + 8);
            }
#pragma unroll
            for (int mi = 0; mi < 2; ++mi)
#pragma unroll
                for (int ni = 0; ni < 4; ++ni) {
                    mma16816(sacc[mi][ni], ah[mi], bhf[ni]);
                    mma16816(sacc[mi][ni], ah[mi], blf[ni]);
                    mma16816(sacc[mi][ni], al[mi], bhf[ni]);
                }
        }

#pragma unroll
        for (int mi = 0; mi < 2; ++mi)
#pragma unroll
            for (int half = 0; half < 2; ++half) {
                float pm = -1e30f;
#pragma unroll
                for (int ni = 0; ni < 4; ++ni) {
                    pm = fmaxf(pm, sacc[mi][ni][half * 2 + 0]);
                    pm = fmaxf(pm, sacc[mi][ni][half * 2 + 1]);
                }
                pm = fmaxf(pm, __shfl_xor_sync(0xffffffffu, pm, 1));
                pm = fmaxf(pm, __shfl_xor_sync(0xffffffffu, pm, 2));
                int row = wrow + mi * 16 + half * 8 + g;
                sMax[row * 2 + kvh] = pm;
            }
        __syncthreads();

        float alpha[2][2];
#pragma unroll
        for (int mi = 0; mi < 2; ++mi)
#pragma unroll
            for (int half = 0; half < 2; ++half) {
                int row = wrow + mi * 16 + half * 8 + g;
                float mt = fmaxf(sMax[row * 2], sMax[row * 2 + 1]) * ATTN_SCALE;
                float mnew = fmaxf(m_run[mi][half], mt);
                alpha[mi][half] = __expf(m_run[mi][half] - mnew);
                m_run[mi][half] = mnew;
            }
#pragma unroll
        for (int mi = 0; mi < 2; ++mi)
#pragma unroll
            for (int ni = 0; ni < 4; ++ni)
#pragma unroll
                for (int r = 0; r < 4; ++r)
                    sacc[mi][ni][r] = __expf(
                        fmaf(sacc[mi][ni][r], ATTN_SCALE, -m_run[mi][r >> 1]));

#pragma unroll
        for (int mi = 0; mi < 2; ++mi)
#pragma unroll
            for (int half = 0; half < 2; ++half) {
                float ps = 0.f;
#pragma unroll
                for (int ni = 0; ni < 4; ++ni)
                    ps += sacc[mi][ni][half * 2 + 0] + sacc[mi][ni][half * 2 + 1];
                ps += __shfl_xor_sync(0xffffffffu, ps, 1);
                ps += __shfl_xor_sync(0xffffffffu, ps, 2);
                int row = wrow + mi * 16 + half * 8 + g;
                sSum[row * 2 + kvh] = ps;
            }

#pragma unroll
        for (int mi = 0; mi < 2; ++mi)
#pragma unroll
            for (int ni = 0; ni < 4; ++ni) {
                int row0 = wrow + mi * 16 + g;
                int idx = kvh * 16 + ni * 4 + tig;
                __nv_bfloat162 hh, ll;
                split2(sacc[mi][ni][0], sacc[mi][ni][1], hh, ll);
                sPh[row0 * 36 + idx] = *reinterpret_cast<uint32_t*>(&hh);
                sPl[row0 * 36 + idx] = *reinterpret_cast<uint32_t*>(&ll);
                split2(sacc[mi][ni][2], sacc[mi][ni][3], hh, ll);
                sPh[(row0 + 8) * 36 + idx] = *reinterpret_cast<uint32_t*>(&hh);
                sPl[(row0 + 8) * 36 + idx] = *reinterpret_cast<uint32_t*>(&ll);
            }

        // ---- Stage V^T [d][kv] from pre-split v (no conversion) ----
#pragma unroll
        for (int it = 0; it < 8; ++it) {
            int id = it * 256 + tid;      // 0..2047
            int j = id >> 5, c = id & 31; // kv row j, bf162 col c (d = 2c,2c+1)
            __nv_bfloat162 hv = *reinterpret_cast<const __nv_bfloat162*>(
                &g_v_hi[base + (size_t)(kt + j) * HD + 2 * c]);
            __nv_bfloat162 lv = *reinterpret_cast<const __nv_bfloat162*>(
                &g_v_lo[base + (size_t)(kt + j) * HD + 2 * c]);
            sKVh[(2 * c + 0) * 72 + j] = __low2bfloat16(hv);
            sKVh[(2 * c + 1) * 72 + j] = __high2bfloat16(hv);
            sKVl[(2 * c + 0) * 72 + j] = __low2bfloat16(lv);
            sKVl[(2 * c + 1) * 72 + j] = __high2bfloat16(lv);
        }
        __syncthreads();

#pragma unroll
        for (int mi = 0; mi < 2; ++mi)
#pragma unroll
            for (int half = 0; half < 2; ++half) {
                int row = wrow + mi * 16 + half * 8 + g;
                float st = sSum[row * 2] + sSum[row * 2 + 1];
                l_run[mi][half] = fmaf(l_run[mi][half], alpha[mi][half], st);
            }
#pragma unroll
        for (int mi = 0; mi < 2; ++mi)
#pragma unroll
            for (int ni = 0; ni < 4; ++ni)
#pragma unroll
                for (int r = 0; r < 4; ++r)
                    oacc[mi][ni][r] *= alpha[mi][r >> 1];

#pragma unroll
        for (int ks = 0; ks < 4; ++ks) {
            uint32_t pah[2][4], pal[2][4];
#pragma unroll
            for (int mi = 0; mi < 2; ++mi) {
                int bidx = (wrow + mi * 16 + g) * 36 + ks * 8 + tig;
                pah[mi][0] = sPh[bidx];
                pah[mi][1] = sPh[bidx + 8 * 36];
                pah[mi][2] = sPh[bidx + 4];
                pah[mi][3] = sPh[bidx + 8 * 36 + 4];
                pal[mi][0] = sPl[bidx];
                pal[mi][1] = sPl[bidx + 8 * 36];
                pal[mi][2] = sPl[bidx + 4];
                pal[mi][3] = sPl[bidx + 8 * 36 + 4];
            }
            uint32_t vbh[4][2], vbl[4][2];
#pragma unroll
            for (int ni = 0; ni < 4; ++ni) {
                const bf16* p = sKVh + (wcol + ni * 8 + g) * 72 + ks * 16 + 2 * tig;
                vbh[ni][0] = *reinterpret_cast<const uint32_t*>(p);
                vbh[ni][1] = *reinterpret_cast<const uint32_t*>(p + 8);
                const bf16* q = sKVl + (wcol + ni * 8 + g) * 72 + ks * 16 + 2 * tig;
                vbl[ni][0] = *reinterpret_cast<const uint32_t*>(q);
                vbl[ni][1] = *reinterpret_cast<const uint32_t*>(q + 8);
            }
#pragma unroll
            for (int mi = 0; mi < 2; ++mi)
#pragma unroll
                for (int ni = 0; ni < 4; ++ni) {
                    mma16816(oacc[mi][ni], pah[mi], vbh[ni]);
                    mma16816(oacc[mi][ni], pah[mi], vbl[ni]);
                    mma16816(oacc[mi][ni], pal[mi], vbh[ni]);
                }
        }
        __syncthreads();
    }

    // ---- Epilogue: normalize and store pre-split ctx [m][768] ----
#pragma unroll
    for (int mi = 0; mi < 2; ++mi) {
        int r0 = wrow + mi * 16 + g;
        float inv0 = 1.f / l_run[mi][0];
        float inv1 = 1.f / l_run[mi][1];
#pragma unroll
        for (int ni = 0; ni < 4; ++ni) {
            int col = wcol + ni * 8 + 2 * tig;
            size_t o0 = (size_t)(b * SEQ + qb + r0) * DMODEL + h * HD + col;
            size_t o1 = (size_t)(b * SEQ + qb + r0 + 8) * DMODEL + h * HD + col;
            __nv_bfloat162 hh, ll;
            split2(oacc[mi][ni][0] * inv0, oacc[mi][ni][1] * inv0, hh, ll);
            *reinterpret_cast<__nv_bfloat162*>(&g_ctx_hi[o0]) = hh;
            *reinterpret_cast<__nv_bfloat162*>(&g_ctx_lo[o0]) = ll;
            split2(oacc[mi][ni][2] * inv1, oacc[mi][ni][3] * inv1, hh, ll);
            *reinterpret_cast<__nv_bfloat162*>(&g_ctx_hi[o1]) = hh;
            *reinterpret_cast<__nv_bfloat162*>(&g_ctx_lo[o1]) = ll;
        }
    }
}

// ---------------------------------------------------------------------------
extern "C" void kernel_launch(void* const* d_in, const int* in_sizes, int n_in,
                              void* d_out, int out_size)
{
    const float* hidden = (const float*)d_in[0];
    const float* w_qkv  = (const float*)d_in[1];
    const float* b_qkv  = (const float*)d_in[2];
    const float* w_proj = (const float*)d_in[3];
    const float* b_proj = (const float*)d_in[4];
    float* out = (float*)d_out;

    cudaFuncSetAttribute(attn_hmma,
                         cudaFuncAttributeMaxDynamicSharedMemorySize, ATTN_SMEM);
    cudaFuncSetAttribute(qkv_gemm_cp,
                         cudaFuncAttributeMaxDynamicSharedMemorySize, GEMM_SMEM);
    cudaFuncSetAttribute(proj_gemm_cp,
                         cudaFuncAttributeMaxDynamicSharedMemorySize, GEMM_SMEM);

    conv_hidden<<<(MTOT * DMODEL / 4) / 256, 256>>>(hidden);
    transpose_wqkv<<<dim3(NQKV / 32, DMODEL / 32), dim3(32, 8)>>>(w_qkv);
    transpose_wproj<<<dim3(DMODEL / 32, DMODEL / 32), dim3(32, 8)>>>(w_proj);

    qkv_gemm_cp<<<dim3(NQKV / 128, MTOT / 128), 256, GEMM_SMEM>>>(b_qkv);
    attn_hmma<<<dim3(SEQ / 128, NH, BATCH), 256, ATTN_SMEM>>>();
    proj_gemm_cp<<<dim3(DMODEL / 128, MTOT / 128), 256, GEMM_SMEM>>>(b_proj, out);
}